// round 13
// baseline (speedup 1.0000x reference)
#include <cuda_runtime.h>
#include <cuda_fp16.h>
#include <cstdint>

#define BB     2
#define LL     2048
#define LTXT   1024
#define DMODEL 512
#define NHEAD  8
#define DHEAD  64
#define WSZ    (DMODEL*DMODEL)

// Scratch (device globals; no allocations allowed)
__device__ __half g_xq[BB*LL*DMODEL];
__device__ __half g_xk[BB*LL*DMODEL];
__device__ __half g_xv[BB*LL*DMODEL];
__device__ __half g_wh[4*WSZ];
__device__ __half g_qh[BB*NHEAD*LL*DHEAD];    // [bh][l][d], pre-scaled log2e/8
__device__ __half g_kh[BB*NHEAD*LL*DHEAD];    // [bh][l][d]
__device__ __half g_vh[BB*NHEAD*LL*DHEAD];    // TRANSPOSED [bh][d][l], pre-mul coef
__device__ __half g_attnh[BB*LL*DMODEL];      // [l][512]
__device__ float  g_coef[BB*LL];
__device__ __half g_kmulh[BB*LL];             // 1.0 (unmasked) or 0.0 (masked)

// ---------------------------------------------------------------------------
// Helpers
// ---------------------------------------------------------------------------
__device__ __forceinline__ uint32_t pk(float lo, float hi) {
    __half2 h = __floats2half2_rn(lo, hi);
    return *reinterpret_cast<uint32_t*>(&h);
}
__device__ __forceinline__ uint32_t pkcvt(float lo, float hi) {
    uint32_t r;
    asm("cvt.rn.f16x2.f32 %0, %1, %2;" : "=r"(r) : "f"(hi), "f"(lo));
    return r;
}
__device__ __forceinline__ uint32_t h2ex2(uint32_t x) {
    uint32_t r;
    asm("ex2.approx.f16x2 %0, %1;" : "=r"(r) : "r"(x));
    return r;
}
__device__ __forceinline__ uint32_t h2mul(uint32_t a, uint32_t b) {
    uint32_t r;
    asm("mul.f16x2 %0, %1, %2;" : "=r"(r) : "r"(a), "r"(b));
    return r;
}
__device__ __forceinline__ float ex2(float x) {
    float r;
    asm("ex2.approx.f32 %0, %1;" : "=f"(r) : "f"(x));
    return r;
}
__device__ __forceinline__ void mma16(float* c,
    uint32_t a0, uint32_t a1, uint32_t a2, uint32_t a3,
    uint32_t b0, uint32_t b1)
{
    asm("mma.sync.aligned.m16n8k16.row.col.f32.f16.f16.f32 "
        "{%0,%1,%2,%3},{%4,%5,%6,%7},{%8,%9},{%0,%1,%2,%3};"
        : "+f"(c[0]), "+f"(c[1]), "+f"(c[2]), "+f"(c[3])
        : "r"(a0), "r"(a1), "r"(a2), "r"(a3), "r"(b0), "r"(b1));
}
__device__ __forceinline__ void ldsm4(uint32_t& r0, uint32_t& r1,
                                      uint32_t& r2, uint32_t& r3, uint32_t addr)
{
    asm volatile("ldmatrix.sync.aligned.m8n8.x4.shared.b16 {%0,%1,%2,%3}, [%4];"
        : "=r"(r0), "=r"(r1), "=r"(r2), "=r"(r3) : "r"(addr));
}
__device__ __forceinline__ void cp_async16(uint32_t saddr, const void* gptr) {
    asm volatile("cp.async.cg.shared.global [%0], [%1], 16;" :: "r"(saddr), "l"(gptr));
}
__device__ __forceinline__ void cp_commit() {
    asm volatile("cp.async.commit_group;");
}

// ---------------------------------------------------------------------------
// fp32 -> fp16 bulk convert (7 tensors)
// ---------------------------------------------------------------------------
struct CvtArgs {
    const float* src[7];
    __half*      dst[7];
    int          n4[7];
};

__global__ void __launch_bounds__(256) cvt_kernel(CvtArgs a)
{
    const int z = blockIdx.y;
    const float4* s = (const float4*)a.src[z];
    uint2* d = (uint2*)a.dst[z];
    const int n4 = a.n4[z];
    for (int i = blockIdx.x*256 + threadIdx.x; i < n4; i += gridDim.x*256) {
        float4 v = s[i];
        d[i] = make_uint2(pk(v.x, v.y), pk(v.z, v.w));
    }
}

// ---------------------------------------------------------------------------
// Mask -> coef (post-softmax weight; 0 iff masked) + multiplicative key mask.
// ---------------------------------------------------------------------------
__global__ void coef_kernel(const float* __restrict__ tm, const float* __restrict__ am)
{
    int b = blockIdx.x;
    int t = threadIdx.x;
    float tv = tm[b*LTXT + t];
    float av = am[b*LTXT + t];
    float ts = tv, as_ = av;
    #pragma unroll
    for (int o = 16; o; o >>= 1) {
        ts  += __shfl_xor_sync(0xffffffffu, ts,  o);
        as_ += __shfl_xor_sync(0xffffffffu, as_, o);
    }
    __shared__ float st[32], sa[32];
    int warp = t >> 5, lane = t & 31;
    if (lane == 0) { st[warp] = ts; sa[warp] = as_; }
    __syncthreads();
    if (warp == 0) {
        ts = st[lane]; as_ = sa[lane];
        #pragma unroll
        for (int o = 16; o; o >>= 1) {
            ts  += __shfl_xor_sync(0xffffffffu, ts,  o);
            as_ += __shfl_xor_sync(0xffffffffu, as_, o);
        }
        if (lane == 0) { st[0] = ts; sa[0] = as_; }
    }
    __syncthreads();
    float tsum = st[0], asum = sa[0], tot = tsum + asum;
    g_coef[b*LL + t]         = tv * (tot / (2.0f * tsum));
    g_coef[b*LL + LTXT + t]  = av * (tot / (2.0f * asum));
    g_kmulh[b*LL + t]        = __float2half(tv == 0.0f ? 0.0f : 1.0f);
    g_kmulh[b*LL + LTXT + t] = __float2half(av == 0.0f ? 0.0f : 1.0f);
}

// ---------------------------------------------------------------------------
// FP16 TC GEMM, 3-stage cp.async, BK=64, ldmatrix.x4 fragment loads.
// ---------------------------------------------------------------------------
#define GAP 36
#define XST (128*GAP)
#define WST (64*GAP)
#define GEMM_SMEM (3*(XST + WST)*4)
#define NKC (DMODEL/64)

struct QkvArgs {
    const __half* X[3];
    const __half* W[3];
    const float*  bias[3];
    __half*       Y[3];
    int           mode[3];
    const float*  coef;
};

template<typename EPI>
__device__ __forceinline__ void gemm_core(
    const __half* __restrict__ X, const __half* __restrict__ W,
    uint32_t* smem, int m0, int n0, EPI epi)
{
    uint32_t* sX = smem;
    uint32_t* sW = smem + 3*XST;

    const int tid  = threadIdx.x;
    const int warp = tid >> 5, lane = tid & 31;
    const int wm = (warp >> 1) * 32;
    const int wn = (warp & 1) * 32;
    const int rowin = lane & 7;
    const int selh  = lane >> 4;
    const int sell  = (lane >> 3) & 1;

    const uint32_t bX = (uint32_t)__cvta_generic_to_shared(sX);
    const uint32_t bW = (uint32_t)__cvta_generic_to_shared(sW);

    auto prefetch = [&](int buf, int k0) {
        #pragma unroll
        for (int i = 0; i < 4; i++) {
            int s = tid + i*256;
            int r = s >> 3, ch = s & 7;
            cp_async16(bX + (buf*XST + r*GAP + ch*4)*4,
                       X + (size_t)(m0 + r)*DMODEL + k0 + ch*8);
        }
        #pragma unroll
        for (int i = 0; i < 2; i++) {
            int s = tid + i*256;
            int r = s >> 3, ch = s & 7;
            cp_async16(bW + (buf*WST + r*GAP + ch*4)*4,
                       W + (size_t)(n0 + r)*DMODEL + k0 + ch*8);
        }
        cp_commit();
    };

    const uint32_t xoff = ((wm + sell*8 + rowin)*GAP + selh*4)*4;
    const uint32_t woff = ((wn + selh*8 + rowin)*GAP + sell*4)*4;

    float c[2][4][4] = {};

    prefetch(0, 0);
    prefetch(1, 64);
    #pragma unroll 1
    for (int kc = 0; kc < NKC; kc++) {
        if (kc + 1 < NKC) asm volatile("cp.async.wait_group 1;");
        else              asm volatile("cp.async.wait_group 0;");
        __syncthreads();
        if (kc + 2 < NKC) prefetch((kc+2)%3, (kc+2)*64);

        const uint32_t xb = bX + (kc%3)*XST*4 + xoff;
        const uint32_t wb = bW + (kc%3)*WST*4 + woff;
        #pragma unroll
        for (int kk = 0; kk < 4; kk++) {
            uint32_t a[2][4];
            ldsm4(a[0][0], a[0][1], a[0][2], a[0][3], xb + kk*32);
            ldsm4(a[1][0], a[1][1], a[1][2], a[1][3], xb + 16*GAP*4 + kk*32);
            #pragma unroll
            for (int njp = 0; njp < 2; njp++) {
                uint32_t b0, b1, b2, b3;
                ldsm4(b0, b1, b2, b3, wb + njp*16*GAP*4 + kk*32);
                mma16(c[0][2*njp  ], a[0][0], a[0][1], a[0][2], a[0][3], b0, b1);
                mma16(c[1][2*njp  ], a[1][0], a[1][1], a[1][2], a[1][3], b0, b1);
                mma16(c[0][2*njp+1], a[0][0], a[0][1], a[0][2], a[0][3], b2, b3);
                mma16(c[1][2*njp+1], a[1][0], a[1][1], a[1][2], a[1][3], b2, b3);
            }
        }
    }

    const int qr = lane >> 2, qc = lane & 3;
    #pragma unroll
    for (int mi = 0; mi < 2; mi++) {
        int row0 = m0 + wm + mi*16 + qr;
        #pragma unroll
        for (int nj = 0; nj < 4; nj++) {
            int col = n0 + wn + nj*8 + qc*2;
            epi(row0, col, c[mi][nj]);
        }
    }
}

__global__ void __launch_bounds__(256) gemm_qkv(QkvArgs args)
{
    extern __shared__ uint32_t smg[];
    const int z = blockIdx.z;
    const float* B = args.bias[z];
    __half* Y = args.Y[z];
    const int mode = args.mode[z];
    const float* coef = args.coef;

    gemm_core(args.X[z], args.W[z], smg, blockIdx.y*128, blockIdx.x*64,
        [&](int row0, int col, float* cc) {
            int row1 = row0 + 8;
            float b0 = B[col], b1 = B[col+1];
            float v00 = cc[0] + b0, v01 = cc[1] + b1;
            float v10 = cc[2] + b0, v11 = cc[3] + b1;
            int h = col >> 6, d = col & 63;
            int bi0 = row0 >> 11, l0 = row0 & 2047;
            int bi1 = row1 >> 11, l1 = row1 & 2047;
            if (mode == 1) {          // Q: 1/8 * log2(e)  (log2-domain softmax)
                const float qs = 0.125f * 1.44269504f;
                v00 *= qs; v01 *= qs; v10 *= qs; v11 *= qs;
            }
            if (mode == 3) {
                float c0 = coef[row0], c1 = coef[row1];
                __half* p = Y + ((size_t)(bi0*NHEAD + h)*DHEAD + d)*LL;  // [bh][d][l]
                p[l0]      = __float2half(v00*c0);
                p[LL + l0] = __float2half(v01*c0);
                p[l1]      = __float2half(v10*c1);
                p[LL + l1] = __float2half(v11*c1);
            } else {
                *(__half2*)(Y + ((size_t)(bi0*NHEAD + h)*LL + l0)*DHEAD + d) =
                    __floats2half2_rn(v00, v01);
                *(__half2*)(Y + ((size_t)(bi1*NHEAD + h)*LL + l1)*DHEAD + d) =
                    __floats2half2_rn(v10, v11);
            }
        });
}

__global__ void __launch_bounds__(256) gemm_out(
    const __half* __restrict__ Xh, const __half* __restrict__ Wh,
    const float* __restrict__ B, float* __restrict__ Y)
{
    extern __shared__ uint32_t smg[];
    gemm_core(Xh, Wh, smg, blockIdx.y*128, blockIdx.x*64,
        [&](int row0, int col, float* cc) {
            float b0 = B[col], b1 = B[col+1];
            *(float2*)(Y + (size_t)row0*DMODEL + col)     = make_float2(cc[0]+b0, cc[1]+b1);
            *(float2*)(Y + (size_t)(row0+8)*DMODEL + col) = make_float2(cc[2]+b0, cc[3]+b1);
        });
}

// ---------------------------------------------------------------------------
// Fused attention v7: cross-tile software pipeline.  S(t+1) mma interleaved
// with PV(t) mma per k-chunk so the tensor pipe stays busy through softmax.
// fp16 m16n8k16 + ldmatrix.x4, log2 softmax, l-via-mma, mult. key mask.
// ---------------------------------------------------------------------------
#define AP 36
#define KT (64*AP)
#define MB 32
#define ATTN_SMEM ((6*KT + 3*MB) * 4)
#define NT (LL/64)

__global__ void __launch_bounds__(256, 2) attn_kernel()
{
    extern __shared__ uint32_t smu[];
    uint32_t* Ks  = smu;                    // [3][64key][AP]
    uint32_t* Vs  = smu + 3*KT;             // [3][64d][AP]  (V^T)
    uint32_t* kms = smu + 6*KT;             // [3][MB] half2 key mask

    const int tid  = threadIdx.x;
    const int warp = tid >> 5, lane = tid & 31;
    const int qr = lane >> 2, qc = lane & 3;
    const int bh = blockIdx.y, bi = bh >> 3, h = bh & 7;
    const int q0 = blockIdx.x * 128;
    const int wrow = warp * 16;
    const int rowin = lane & 7;
    const int selh  = lane >> 4;
    const int sell  = (lane >> 3) & 1;

    const __half* kbase = g_kh + (size_t)bh * LL * DHEAD;
    const __half* vbase = g_vh + (size_t)bh * DHEAD * LL;
    const float*  cbase = g_coef + bi*LL;
    const __half* mbase = g_kmulh + bi*LL;

    const uint32_t sK = (uint32_t)__cvta_generic_to_shared(Ks);
    const uint32_t sV = (uint32_t)__cvta_generic_to_shared(Vs);
    const uint32_t sM = (uint32_t)__cvta_generic_to_shared(kms);

    auto prefetch = [&](int buf, int k0) {
        #pragma unroll
        for (int i = 0; i < 2; i++) {
            int s = tid + i*256;
            int r = s >> 3, ch = s & 7;
            cp_async16(sK + (buf*KT + r*AP + ch*4)*4,
                       kbase + (size_t)(k0 + r)*DHEAD + ch*8);
            cp_async16(sV + (buf*KT + r*AP + ch*4)*4,
                       vbase + (size_t)r*LL + k0 + ch*8);
        }
        if (tid < 8)
            cp_async16(sM + (buf*MB + tid*4)*4, mbase + k0 + tid*8);
        cp_commit();
    };

    prefetch(0, 0);
    prefetch(1, 64);

    // ---- Q fragments straight from gmem (fp16, pre-scaled log2e/8) ----
    const uint32_t* qrow0 =
        (const uint32_t*)(g_qh + ((size_t)bh*LL + q0 + wrow + qr)*DHEAD);
    const uint32_t* qrow1 = qrow0 + 8*(DHEAD/2);
    uint32_t aQ[4][4];
    #pragma unroll
    for (int kk = 0; kk < 4; kk++) {
        aQ[kk][0] = qrow0[kk*8 + qc];
        aQ[kk][1] = qrow1[kk*8 + qc];
        aQ[kk][2] = qrow0[kk*8 + qc + 4];
        aQ[kk][3] = qrow1[kk*8 + qc + 4];
    }
    const bool q0ok = (cbase[q0 + wrow + qr]     != 0.0f);
    const bool q1ok = (cbase[q0 + wrow + qr + 8] != 0.0f);

    const uint32_t fragoff = (((selh*8 + rowin)*AP) + sell*4)*4;
    const uint32_t bOnes = (qr == 0) ? 0x3C003C00u : 0u;

    float o[8][4] = {};
    float ol[4] = {};
    float m0 = -1e30f, m1 = -1e30f;
    float s[8][4];

    // ---- prologue: S(0) ----
    asm volatile("cp.async.wait_group 1;");
    __syncthreads();
    {
        const uint32_t kb0 = sK + fragoff;        // buffer 0
        #pragma unroll
        for (int j = 0; j < 8; j++) { s[j][0]=0; s[j][1]=0; s[j][2]=0; s[j][3]=0; }
        #pragma unroll
        for (int kk = 0; kk < 4; kk++) {
            #pragma unroll
            for (int jp = 0; jp < 4; jp++) {
                uint32_t b0, b1, b2, b3;
                ldsm4(b0, b1, b2, b3, kb0 + (jp*16*AP)*4 + kk*32);
                mma16(s[2*jp  ], aQ[kk][0], aQ[kk][1], aQ[kk][2], aQ[kk][3], b0, b1);
                mma16(s[2*jp+1], aQ[kk][0], aQ[kk][1], aQ[kk][2], aQ[kk][3], b2, b3);
            }
        }
    }

    int vbuf = 0, kbuf = 1, wbuf = 2;

    #pragma unroll 1
    for (int t = 0; t < NT; t++) {
        // ---- softmax on s = S(t): q-mask, max, rescale ----
        if (!q0ok) {
            #pragma unroll
            for (int j = 0; j < 8; j++) { s[j][0] = 0.0f; s[j][1] = 0.0f; }
        }
        if (!q1ok) {
            #pragma unroll
            for (int j = 0; j < 8; j++) { s[j][2] = 0.0f; s[j][3] = 0.0f; }
        }
        float mx0 = -1e30f, mx1 = -1e30f;
        #pragma unroll
        for (int j = 0; j < 8; j++) {
            mx0 = fmaxf(mx0, fmaxf(s[j][0], s[j][1]));
            mx1 = fmaxf(mx1, fmaxf(s[j][2], s[j][3]));
        }
        mx0 = fmaxf(mx0, __shfl_xor_sync(0xffffffffu, mx0, 1));
        mx0 = fmaxf(mx0, __shfl_xor_sync(0xffffffffu, mx0, 2));
        mx1 = fmaxf(mx1, __shfl_xor_sync(0xffffffffu, mx1, 1));
        mx1 = fmaxf(mx1, __shfl_xor_sync(0xffffffffu, mx1, 2));
        if (__any_sync(0xffffffffu, (mx0 > m0) | (mx1 > m1))) {
            float nm0 = fmaxf(m0, mx0), nm1 = fmaxf(m1, mx1);
            float sc0 = ex2(m0 - nm0), sc1 = ex2(m1 - nm1);
            #pragma unroll
            for (int j = 0; j < 8; j++) {
                o[j][0] *= sc0; o[j][1] *= sc0;
                o[j][2] *= sc1; o[j][3] *= sc1;
            }
            ol[0] *= sc0; ol[1] *= sc0;
            ol[2] *= sc1; ol[3] *= sc1;
            m0 = nm0;  m1 = nm1;
        }

        const bool more = (t + 1 < NT);
        if (more) {
            asm volatile("cp.async.wait_group 0;");   // tile t+1 fully landed
            __syncthreads();                          // all warps done reading t-1
            if (t + 2 < NT) prefetch(wbuf, (t+2)*64); // overwrites old t-1 buffer
        }

        const uint32_t kb_a = sK + kbuf*KT*4 + fragoff;   // K(t+1)
        const uint32_t vb_a = sV + vbuf*KT*4 + fragoff;   // V(t)
        const uint32_t* km  = kms + vbuf*MB;              // mask(t)

        // ---- fused: a-frags(t) -> [S(t+1) chunk] + PV(t) chunk + l-mma ----
        float sn[8][4];
        if (more) {
            #pragma unroll
            for (int j = 0; j < 8; j++) { sn[j][0]=0; sn[j][1]=0; sn[j][2]=0; sn[j][3]=0; }
        }
        #pragma unroll
        for (int jj = 0; jj < 4; jj++) {
            uint32_t a0 = h2ex2(pkcvt(s[2*jj  ][0] - m0, s[2*jj  ][1] - m0));
            uint32_t a1 = h2ex2(pkcvt(s[2*jj  ][2] - m1, s[2*jj  ][3] - m1));
            uint32_t a2 = h2ex2(pkcvt(s[2*jj+1][0] - m0, s[2*jj+1][1] - m0));
            uint32_t a3 = h2ex2(pkcvt(s[2*jj+1][2] - m1, s[2*jj+1][3] - m1));
            uint32_t km_e = km[(2*jj  )*4 + qc];
            uint32_t km_o = km[(2*jj+1)*4 + qc];
            if (q0ok) { a0 = h2mul(a0, km_e); a2 = h2mul(a2, km_o); }
            if (q1ok) { a1 = h2mul(a1, km_e); a3 = h2mul(a3, km_o); }

            if (more) {   // S(t+1), k-chunk kk=jj — independent of PV below
                #pragma unroll
                for (int jp = 0; jp < 4; jp++) {
                    uint32_t b0, b1, b2, b3;
                    ldsm4(b0, b1, b2, b3, kb_a + (jp*16*AP)*4 + jj*32);
                    mma16(sn[2*jp  ], aQ[jj][0], aQ[jj][1], aQ[jj][2], aQ[jj][3], b0, b1);
                    mma16(sn[2*jp+1], aQ[jj][0], aQ[jj][1], aQ[jj][2], aQ[jj][3], b2, b3);
                }
            }
            #pragma unroll
            for (int njp = 0; njp < 4; njp++) {
                uint32_t b0, b1, b2, b3;
                ldsm4(b0, b1, b2, b3, vb_a + (njp*16*AP)*4 + jj*32);
                mma16(o[2*njp  ], a0, a1, a2, a3, b0, b1);
                mma16(o[2*njp+1], a0, a1, a2, a3, b2, b3);
            }
            mma16(ol, a0, a1, a2, a3, bOnes, bOnes);
        }
        if (more) {
            #pragma unroll
            for (int j = 0; j < 8; j++) {
                s[j][0]=sn[j][0]; s[j][1]=sn[j][1]; s[j][2]=sn[j][2]; s[j][3]=sn[j][3];
            }
        }
        int old = vbuf; vbuf = kbuf; kbuf = wbuf; wbuf = old;
    }

    // ---- epilogue: recover l from qc==0 lanes, normalize, write fp16 ----
    float lq0 = __shfl_sync(0xffffffffu, ol[0], lane & ~3);
    float lq1 = __shfl_sync(0xffffffffu, ol[2], lane & ~3);
    float inv0 = 1.0f / lq0, inv1 = 1.0f / lq1;
    int r0 = q0 + wrow + qr, r1 = r0 + 8;
    #pragma unroll
    for (int j = 0; j < 8; j++) {
        int d = h*64 + j*8 + qc*2;
        *(__half2*)(g_attnh + ((size_t)(bi*LL + r0))*DMODEL + d) =
            __floats2half2_rn(o[j][0]*inv0, o[j][1]*inv0);
        *(__half2*)(g_attnh + ((size_t)(bi*LL + r1))*DMODEL + d) =
            __floats2half2_rn(o[j][2]*inv1, o[j][3]*inv1);
    }
}

// ---------------------------------------------------------------------------
extern "C" void kernel_launch(void* const* d_in, const int* in_sizes, int n_in,
                              void* d_out, int out_size)
{
    const float* q  = (const float*)d_in[0];
    const float* k  = (const float*)d_in[1];
    const float* v  = (const float*)d_in[2];
    const float* tm = (const float*)d_in[3];
    const float* am = (const float*)d_in[4];
    const float* wq = (const float*)d_in[6];
    const float* bq = (const float*)d_in[7];
    const float* wk = (const float*)d_in[8];
    const float* bk = (const float*)d_in[9];
    const float* wv = (const float*)d_in[10];
    const float* bv = (const float*)d_in[11];
    const float* wo = (const float*)d_in[12];
    const float* bo = (const float*)d_in[13];
    float* out = (float*)d_out;

    __half *xq, *xk, *xv, *wh, *gq, *gk, *gv, *gattn;
    float *gcoef;
    cudaGetSymbolAddress((void**)&xq,    g_xq);
    cudaGetSymbolAddress((void**)&xk,    g_xk);
    cudaGetSymbolAddress((void**)&xv,    g_xv);
    cudaGetSymbolAddress((void**)&wh,    g_wh);
    cudaGetSymbolAddress((void**)&gq,    g_qh);
    cudaGetSymbolAddress((void**)&gk,    g_kh);
    cudaGetSymbolAddress((void**)&gv,    g_vh);
    cudaGetSymbolAddress((void**)&gattn, g_attnh);
    cudaGetSymbolAddress((void**)&gcoef, g_coef);

    cudaFuncSetAttribute(gemm_qkv, cudaFuncAttributeMaxDynamicSharedMemorySize, GEMM_SMEM);
    cudaFuncSetAttribute(gemm_out, cudaFuncAttributeMaxDynamicSharedMemorySize, GEMM_SMEM);
    cudaFuncSetAttribute(attn_kernel, cudaFuncAttributeMaxDynamicSharedMemorySize, ATTN_SMEM);

    const int NBIG = BB*LL*DMODEL/4;
    const int NW   = WSZ/4;
    CvtArgs ca;
    ca.src[0] = q;  ca.dst[0] = xq;         ca.n4[0] = NBIG;
    ca.src[1] = k;  ca.dst[1] = xk;         ca.n4[1] = NBIG;
    ca.src[2] = v;  ca.dst[2] = xv;         ca.n4[2] = NBIG;
    ca.src[3] = wq; ca.dst[3] = wh;         ca.n4[3] = NW;
    ca.src[4] = wk; ca.dst[4] = wh + WSZ;   ca.n4[4] = NW;
    ca.src[5] = wv; ca.dst[5] = wh + 2*WSZ; ca.n4[5] = NW;
    ca.src[6] = wo; ca.dst[6] = wh + 3*WSZ; ca.n4[6] = NW;
    cvt_kernel<<<dim3(256, 7), 256>>>(ca);

    coef_kernel<<<2, 1024>>>(tm, am);

    QkvArgs qkv;
    qkv.X[0] = xq; qkv.X[1] = xk; qkv.X[2] = xv;
    qkv.W[0] = wh; qkv.W[1] = wh + WSZ; qkv.W[2] = wh + 2*WSZ;
    qkv.bias[0] = bq; qkv.bias[1] = bk; qkv.bias[2] = bv;
    qkv.Y[0] = gq; qkv.Y[1] = gk; qkv.Y[2] = gv;
    qkv.mode[0] = 1; qkv.mode[1] = 2; qkv.mode[2] = 3;
    qkv.coef = gcoef;
    gemm_qkv<<<dim3(8, 32, 3), 256, GEMM_SMEM>>>(qkv);

    attn_kernel<<<dim3(16, 16), 256, ATTN_SMEM>>>();

    gemm_out<<<dim3(8, 32), 256, GEMM_SMEM>>>(gattn, wh + 3*WSZ, bo, out);
}

// round 14
// speedup vs baseline: 1.4036x; 1.4036x over previous
#include <cuda_runtime.h>
#include <cuda_fp16.h>
#include <cstdint>

#define BB     2
#define LL     2048
#define LTXT   1024
#define DMODEL 512
#define NHEAD  8
#define DHEAD  64
#define WSZ    (DMODEL*DMODEL)

// Scratch (device globals; no allocations allowed)
__device__ __half g_xq[BB*LL*DMODEL];
__device__ __half g_xk[BB*LL*DMODEL];
__device__ __half g_xv[BB*LL*DMODEL];
__device__ __half g_wh[4*WSZ];
__device__ __half g_qh[BB*NHEAD*LL*DHEAD];    // [bh][l][d], pre-scaled log2e/8
__device__ __half g_kh[BB*NHEAD*LL*DHEAD];    // [bh][l][d]
__device__ __half g_vh[BB*NHEAD*LL*DHEAD];    // TRANSPOSED [bh][d][l], pre-mul coef
__device__ __half g_attnh[BB*LL*DMODEL];      // [l][512]
__device__ float  g_coef[BB*LL];
__device__ __half g_kmulh[BB*LL];             // 1.0 (unmasked) or 0.0 (masked)

// ---------------------------------------------------------------------------
// Helpers
// ---------------------------------------------------------------------------
__device__ __forceinline__ uint32_t pk(float lo, float hi) {
    __half2 h = __floats2half2_rn(lo, hi);
    return *reinterpret_cast<uint32_t*>(&h);
}
__device__ __forceinline__ uint32_t pkcvt(float lo, float hi) {
    uint32_t r;
    asm("cvt.rn.f16x2.f32 %0, %1, %2;" : "=r"(r) : "f"(hi), "f"(lo));
    return r;
}
__device__ __forceinline__ uint32_t h2ex2(uint32_t x) {
    uint32_t r;
    asm("ex2.approx.f16x2 %0, %1;" : "=r"(r) : "r"(x));
    return r;
}
__device__ __forceinline__ uint32_t h2mul(uint32_t a, uint32_t b) {
    uint32_t r;
    asm("mul.f16x2 %0, %1, %2;" : "=r"(r) : "r"(a), "r"(b));
    return r;
}
__device__ __forceinline__ float ex2(float x) {
    float r;
    asm("ex2.approx.f32 %0, %1;" : "=f"(r) : "f"(x));
    return r;
}
__device__ __forceinline__ void mma16(float* c,
    uint32_t a0, uint32_t a1, uint32_t a2, uint32_t a3,
    uint32_t b0, uint32_t b1)
{
    asm("mma.sync.aligned.m16n8k16.row.col.f32.f16.f16.f32 "
        "{%0,%1,%2,%3},{%4,%5,%6,%7},{%8,%9},{%0,%1,%2,%3};"
        : "+f"(c[0]), "+f"(c[1]), "+f"(c[2]), "+f"(c[3])
        : "r"(a0), "r"(a1), "r"(a2), "r"(a3), "r"(b0), "r"(b1));
}
__device__ __forceinline__ void ldsm4(uint32_t& r0, uint32_t& r1,
                                      uint32_t& r2, uint32_t& r3, uint32_t addr)
{
    asm volatile("ldmatrix.sync.aligned.m8n8.x4.shared.b16 {%0,%1,%2,%3}, [%4];"
        : "=r"(r0), "=r"(r1), "=r"(r2), "=r"(r3) : "r"(addr));
}
__device__ __forceinline__ void cp_async16(uint32_t saddr, const void* gptr) {
    asm volatile("cp.async.cg.shared.global [%0], [%1], 16;" :: "r"(saddr), "l"(gptr));
}
__device__ __forceinline__ void cp_commit() {
    asm volatile("cp.async.commit_group;");
}

// ---------------------------------------------------------------------------
// fp32 -> fp16 bulk convert (7 tensors)
// ---------------------------------------------------------------------------
struct CvtArgs {
    const float* src[7];
    __half*      dst[7];
    int          n4[7];
};

__global__ void __launch_bounds__(256) cvt_kernel(CvtArgs a)
{
    const int z = blockIdx.y;
    const float4* s = (const float4*)a.src[z];
    uint2* d = (uint2*)a.dst[z];
    const int n4 = a.n4[z];
    for (int i = blockIdx.x*256 + threadIdx.x; i < n4; i += gridDim.x*256) {
        float4 v = s[i];
        d[i] = make_uint2(pk(v.x, v.y), pk(v.z, v.w));
    }
}

// ---------------------------------------------------------------------------
// Mask -> coef (post-softmax weight; 0 iff masked) + multiplicative key mask.
// ---------------------------------------------------------------------------
__global__ void coef_kernel(const float* __restrict__ tm, const float* __restrict__ am)
{
    int b = blockIdx.x;
    int t = threadIdx.x;
    float tv = tm[b*LTXT + t];
    float av = am[b*LTXT + t];
    float ts = tv, as_ = av;
    #pragma unroll
    for (int o = 16; o; o >>= 1) {
        ts  += __shfl_xor_sync(0xffffffffu, ts,  o);
        as_ += __shfl_xor_sync(0xffffffffu, as_, o);
    }
    __shared__ float st[32], sa[32];
    int warp = t >> 5, lane = t & 31;
    if (lane == 0) { st[warp] = ts; sa[warp] = as_; }
    __syncthreads();
    if (warp == 0) {
        ts = st[lane]; as_ = sa[lane];
        #pragma unroll
        for (int o = 16; o; o >>= 1) {
            ts  += __shfl_xor_sync(0xffffffffu, ts,  o);
            as_ += __shfl_xor_sync(0xffffffffu, as_, o);
        }
        if (lane == 0) { st[0] = ts; sa[0] = as_; }
    }
    __syncthreads();
    float tsum = st[0], asum = sa[0], tot = tsum + asum;
    g_coef[b*LL + t]         = tv * (tot / (2.0f * tsum));
    g_coef[b*LL + LTXT + t]  = av * (tot / (2.0f * asum));
    g_kmulh[b*LL + t]        = __float2half(tv == 0.0f ? 0.0f : 1.0f);
    g_kmulh[b*LL + LTXT + t] = __float2half(av == 0.0f ? 0.0f : 1.0f);
}

// ---------------------------------------------------------------------------
// FP16 TC GEMM, 2-stage cp.async (smem 55KB -> 3 CTAs/SM), BK=64,
// ldmatrix.x4 fragment loads.  Block 128x64, 256 threads, warp 32x32.
// ---------------------------------------------------------------------------
#define GAP 36
#define XST (128*GAP)
#define WST (64*GAP)
#define GEMM_SMEM (2*(XST + WST)*4)
#define NKC (DMODEL/64)

struct QkvArgs {
    const __half* X[3];
    const __half* W[3];
    const float*  bias[3];
    __half*       Y[3];
    int           mode[3];
    const float*  coef;
};

template<typename EPI>
__device__ __forceinline__ void gemm_core(
    const __half* __restrict__ X, const __half* __restrict__ W,
    uint32_t* smem, int m0, int n0, EPI epi)
{
    uint32_t* sX = smem;
    uint32_t* sW = smem + 2*XST;

    const int tid  = threadIdx.x;
    const int warp = tid >> 5, lane = tid & 31;
    const int wm = (warp >> 1) * 32;
    const int wn = (warp & 1) * 32;
    const int rowin = lane & 7;
    const int selh  = lane >> 4;
    const int sell  = (lane >> 3) & 1;

    const uint32_t bX = (uint32_t)__cvta_generic_to_shared(sX);
    const uint32_t bW = (uint32_t)__cvta_generic_to_shared(sW);

    auto prefetch = [&](int buf, int k0) {
        #pragma unroll
        for (int i = 0; i < 4; i++) {
            int s = tid + i*256;
            int r = s >> 3, ch = s & 7;
            cp_async16(bX + (buf*XST + r*GAP + ch*4)*4,
                       X + (size_t)(m0 + r)*DMODEL + k0 + ch*8);
        }
        #pragma unroll
        for (int i = 0; i < 2; i++) {
            int s = tid + i*256;
            int r = s >> 3, ch = s & 7;
            cp_async16(bW + (buf*WST + r*GAP + ch*4)*4,
                       W + (size_t)(n0 + r)*DMODEL + k0 + ch*8);
        }
        cp_commit();
    };

    const uint32_t xoff = ((wm + sell*8 + rowin)*GAP + selh*4)*4;
    const uint32_t woff = ((wn + selh*8 + rowin)*GAP + sell*4)*4;

    float c[2][4][4] = {};

    prefetch(0, 0);
    #pragma unroll 1
    for (int kc = 0; kc < NKC; kc++) {
        asm volatile("cp.async.wait_group 0;");   // buffer kc&1 landed
        __syncthreads();                          // prev reads done before overwrite
        if (kc + 1 < NKC) prefetch((kc+1) & 1, (kc+1)*64);

        const uint32_t xb = bX + (kc & 1)*XST*4 + xoff;
        const uint32_t wb = bW + (kc & 1)*WST*4 + woff;
        #pragma unroll
        for (int kk = 0; kk < 4; kk++) {
            uint32_t a[2][4];
            ldsm4(a[0][0], a[0][1], a[0][2], a[0][3], xb + kk*32);
            ldsm4(a[1][0], a[1][1], a[1][2], a[1][3], xb + 16*GAP*4 + kk*32);
            #pragma unroll
            for (int njp = 0; njp < 2; njp++) {
                uint32_t b0, b1, b2, b3;
                ldsm4(b0, b1, b2, b3, wb + njp*16*GAP*4 + kk*32);
                mma16(c[0][2*njp  ], a[0][0], a[0][1], a[0][2], a[0][3], b0, b1);
                mma16(c[1][2*njp  ], a[1][0], a[1][1], a[1][2], a[1][3], b0, b1);
                mma16(c[0][2*njp+1], a[0][0], a[0][1], a[0][2], a[0][3], b2, b3);
                mma16(c[1][2*njp+1], a[1][0], a[1][1], a[1][2], a[1][3], b2, b3);
            }
        }
    }

    const int qr = lane >> 2, qc = lane & 3;
    #pragma unroll
    for (int mi = 0; mi < 2; mi++) {
        int row0 = m0 + wm + mi*16 + qr;
        #pragma unroll
        for (int nj = 0; nj < 4; nj++) {
            int col = n0 + wn + nj*8 + qc*2;
            epi(row0, col, c[mi][nj]);
        }
    }
}

__global__ void __launch_bounds__(256, 3) gemm_qkv(QkvArgs args)
{
    extern __shared__ uint32_t smg[];
    const int z = blockIdx.z;
    const float* B = args.bias[z];
    __half* Y = args.Y[z];
    const int mode = args.mode[z];
    const float* coef = args.coef;

    gemm_core(args.X[z], args.W[z], smg, blockIdx.y*128, blockIdx.x*64,
        [&](int row0, int col, float* cc) {
            int row1 = row0 + 8;
            float b0 = B[col], b1 = B[col+1];
            float v00 = cc[0] + b0, v01 = cc[1] + b1;
            float v10 = cc[2] + b0, v11 = cc[3] + b1;
            int h = col >> 6, d = col & 63;
            int bi0 = row0 >> 11, l0 = row0 & 2047;
            int bi1 = row1 >> 11, l1 = row1 & 2047;
            if (mode == 1) {          // Q: 1/8 * log2(e)  (log2-domain softmax)
                const float qs = 0.125f * 1.44269504f;
                v00 *= qs; v01 *= qs; v10 *= qs; v11 *= qs;
            }
            if (mode == 3) {
                float c0 = coef[row0], c1 = coef[row1];
                __half* p = Y + ((size_t)(bi0*NHEAD + h)*DHEAD + d)*LL;  // [bh][d][l]
                p[l0]      = __float2half(v00*c0);
                p[LL + l0] = __float2half(v01*c0);
                p[l1]      = __float2half(v10*c1);
                p[LL + l1] = __float2half(v11*c1);
            } else {
                *(__half2*)(Y + ((size_t)(bi0*NHEAD + h)*LL + l0)*DHEAD + d) =
                    __floats2half2_rn(v00, v01);
                *(__half2*)(Y + ((size_t)(bi1*NHEAD + h)*LL + l1)*DHEAD + d) =
                    __floats2half2_rn(v10, v11);
            }
        });
}

__global__ void __launch_bounds__(256, 3) gemm_out(
    const __half* __restrict__ Xh, const __half* __restrict__ Wh,
    const float* __restrict__ B, float* __restrict__ Y)
{
    extern __shared__ uint32_t smg[];
    gemm_core(Xh, Wh, smg, blockIdx.y*128, blockIdx.x*64,
        [&](int row0, int col, float* cc) {
            float b0 = B[col], b1 = B[col+1];
            *(float2*)(Y + (size_t)row0*DMODEL + col)     = make_float2(cc[0]+b0, cc[1]+b1);
            *(float2*)(Y + (size_t)(row0+8)*DMODEL + col) = make_float2(cc[2]+b0, cc[3]+b1);
        });
}

// ---------------------------------------------------------------------------
// Fused attention (R12 design): fp16 m16n8k16 + ldmatrix.x4, log2 softmax,
// l computed BY mma (ones B-frag), multiplicative half2 key mask, f16x2 ex2.
// BM=128, BN=64, 256 threads, 2 CTAs/SM.
// ---------------------------------------------------------------------------
#define AP 36
#define KT (64*AP)
#define MB 32
#define ATTN_SMEM ((6*KT + 3*MB) * 4)
#define NT (LL/64)

__global__ void __launch_bounds__(256, 2) attn_kernel()
{
    extern __shared__ uint32_t smu[];
    uint32_t* Ks  = smu;                    // [3][64key][AP]
    uint32_t* Vs  = smu + 3*KT;             // [3][64d][AP]  (V^T)
    uint32_t* kms = smu + 6*KT;             // [3][MB] half2 key mask

    const int tid  = threadIdx.x;
    const int warp = tid >> 5, lane = tid & 31;
    const int qr = lane >> 2, qc = lane & 3;
    const int bh = blockIdx.y, bi = bh >> 3, h = bh & 7;
    const int q0 = blockIdx.x * 128;
    const int wrow = warp * 16;
    const int rowin = lane & 7;
    const int selh  = lane >> 4;
    const int sell  = (lane >> 3) & 1;

    const __half* kbase = g_kh + (size_t)bh * LL * DHEAD;
    const __half* vbase = g_vh + (size_t)bh * DHEAD * LL;
    const float*  cbase = g_coef + bi*LL;
    const __half* mbase = g_kmulh + bi*LL;

    const uint32_t sK = (uint32_t)__cvta_generic_to_shared(Ks);
    const uint32_t sV = (uint32_t)__cvta_generic_to_shared(Vs);
    const uint32_t sM = (uint32_t)__cvta_generic_to_shared(kms);

    auto prefetch = [&](int buf, int k0) {
        #pragma unroll
        for (int i = 0; i < 2; i++) {
            int s = tid + i*256;
            int r = s >> 3, ch = s & 7;
            cp_async16(sK + (buf*KT + r*AP + ch*4)*4,
                       kbase + (size_t)(k0 + r)*DHEAD + ch*8);
            cp_async16(sV + (buf*KT + r*AP + ch*4)*4,
                       vbase + (size_t)r*LL + k0 + ch*8);
        }
        if (tid < 8)
            cp_async16(sM + (buf*MB + tid*4)*4, mbase + k0 + tid*8);
        cp_commit();
    };

    prefetch(0, 0);
    prefetch(1, 64);

    // ---- Q fragments straight from gmem (fp16, pre-scaled log2e/8) ----
    const uint32_t* qrow0 =
        (const uint32_t*)(g_qh + ((size_t)bh*LL + q0 + wrow + qr)*DHEAD);
    const uint32_t* qrow1 = qrow0 + 8*(DHEAD/2);
    uint32_t aQ[4][4];
    #pragma unroll
    for (int kk = 0; kk < 4; kk++) {
        aQ[kk][0] = qrow0[kk*8 + qc];
        aQ[kk][1] = qrow1[kk*8 + qc];
        aQ[kk][2] = qrow0[kk*8 + qc + 4];
        aQ[kk][3] = qrow1[kk*8 + qc + 4];
    }
    const bool q0ok = (cbase[q0 + wrow + qr]     != 0.0f);
    const bool q1ok = (cbase[q0 + wrow + qr + 8] != 0.0f);

    const uint32_t fragoff = (((selh*8 + rowin)*AP) + sell*4)*4;
    const uint32_t bOnes = (qr == 0) ? 0x3C003C00u : 0u;  // ones col-0 B frag (l-mma)

    float o[8][4] = {};
    float ol[4] = {};                       // l accumulator c-frag (col0 @ qc==0)
    float m0 = -1e30f, m1 = -1e30f;
    int buf = 0;

    #pragma unroll 1
    for (int t = 0; t < NT; t++) {
        if (t + 1 < NT) asm volatile("cp.async.wait_group 1;");
        else            asm volatile("cp.async.wait_group 0;");
        __syncthreads();
        if (t + 2 < NT) {
            int nb = buf + 2; if (nb >= 3) nb -= 3;
            prefetch(nb, (t+2)*64);
        }

        const uint32_t kb_a = sK + buf*KT*4 + fragoff;
        const uint32_t vb_a = sV + buf*KT*4 + fragoff;
        const uint32_t* km  = kms + buf*MB;
        buf++; if (buf == 3) buf = 0;

        // ---- S = (Q·log2e/8) @ K^T ----
        float s[8][4] = {};
        #pragma unroll
        for (int kk = 0; kk < 4; kk++) {
            #pragma unroll
            for (int jp = 0; jp < 4; jp++) {
                uint32_t b0, b1, b2, b3;
                ldsm4(b0, b1, b2, b3, kb_a + (jp*16*AP)*4 + kk*32);
                mma16(s[2*jp  ], aQ[kk][0], aQ[kk][1], aQ[kk][2], aQ[kk][3], b0, b1);
                mma16(s[2*jp+1], aQ[kk][0], aQ[kk][1], aQ[kk][2], aQ[kk][3], b2, b3);
            }
        }

        // ---- q-masked rows -> 0 (uniform softmax, l=2048) ----
        if (!q0ok) {
            #pragma unroll
            for (int j = 0; j < 8; j++) { s[j][0] = 0.0f; s[j][1] = 0.0f; }
        }
        if (!q1ok) {
            #pragma unroll
            for (int j = 0; j < 8; j++) { s[j][2] = 0.0f; s[j][3] = 0.0f; }
        }

        // ---- online softmax max ----
        float mx0 = -1e30f, mx1 = -1e30f;
        #pragma unroll
        for (int j = 0; j < 8; j++) {
            mx0 = fmaxf(mx0, fmaxf(s[j][0], s[j][1]));
            mx1 = fmaxf(mx1, fmaxf(s[j][2], s[j][3]));
        }
        mx0 = fmaxf(mx0, __shfl_xor_sync(0xffffffffu, mx0, 1));
        mx0 = fmaxf(mx0, __shfl_xor_sync(0xffffffffu, mx0, 2));
        mx1 = fmaxf(mx1, __shfl_xor_sync(0xffffffffu, mx1, 1));
        mx1 = fmaxf(mx1, __shfl_xor_sync(0xffffffffu, mx1, 2));

        if (__any_sync(0xffffffffu, (mx0 > m0) | (mx1 > m1))) {
            float nm0 = fmaxf(m0, mx0), nm1 = fmaxf(m1, mx1);
            float sc0 = ex2(m0 - nm0), sc1 = ex2(m1 - nm1);
            #pragma unroll
            for (int j = 0; j < 8; j++) {
                o[j][0] *= sc0; o[j][1] *= sc0;
                o[j][2] *= sc1; o[j][3] *= sc1;
            }
            ol[0] *= sc0; ol[1] *= sc0;
            ol[2] *= sc1; ol[3] *= sc1;
            m0 = nm0;  m1 = nm1;
        }

        // ---- exp2 (f16x2) -> masked A-frags -> PV mma + l-mma ----
        #pragma unroll
        for (int jj = 0; jj < 4; jj++) {
            uint32_t a0 = h2ex2(pkcvt(s[2*jj  ][0] - m0, s[2*jj  ][1] - m0));
            uint32_t a1 = h2ex2(pkcvt(s[2*jj  ][2] - m1, s[2*jj  ][3] - m1));
            uint32_t a2 = h2ex2(pkcvt(s[2*jj+1][0] - m0, s[2*jj+1][1] - m0));
            uint32_t a3 = h2ex2(pkcvt(s[2*jj+1][2] - m1, s[2*jj+1][3] - m1));

            uint32_t km_e = km[(2*jj  )*4 + qc];   // keys 16jj   + 2qc,+1
            uint32_t km_o = km[(2*jj+1)*4 + qc];   // keys 16jj+8 + 2qc,+1
            if (q0ok) { a0 = h2mul(a0, km_e); a2 = h2mul(a2, km_o); }
            if (q1ok) { a1 = h2mul(a1, km_e); a3 = h2mul(a3, km_o); }

            #pragma unroll
            for (int njp = 0; njp < 4; njp++) {
                uint32_t b0, b1, b2, b3;
                ldsm4(b0, b1, b2, b3, vb_a + (njp*16*AP)*4 + jj*32);
                mma16(o[2*njp  ], a0, a1, a2, a3, b0, b1);
                mma16(o[2*njp+1], a0, a1, a2, a3, b2, b3);
            }
            mma16(ol, a0, a1, a2, a3, bOnes, bOnes);   // l += row-sums
        }
    }

    // ---- epilogue: recover l from qc==0 lanes, normalize, write fp16 ----
    float lq0 = __shfl_sync(0xffffffffu, ol[0], lane & ~3);
    float lq1 = __shfl_sync(0xffffffffu, ol[2], lane & ~3);
    float inv0 = 1.0f / lq0, inv1 = 1.0f / lq1;
    int r0 = q0 + wrow + qr, r1 = r0 + 8;
    #pragma unroll
    for (int j = 0; j < 8; j++) {
        int d = h*64 + j*8 + qc*2;
        *(__half2*)(g_attnh + ((size_t)(bi*LL + r0))*DMODEL + d) =
            __floats2half2_rn(o[j][0]*inv0, o[j][1]*inv0);
        *(__half2*)(g_attnh + ((size_t)(bi*LL + r1))*DMODEL + d) =
            __floats2half2_rn(o[j][2]*inv1, o[j][3]*inv1);
    }
}

// ---------------------------------------------------------------------------
extern "C" void kernel_launch(void* const* d_in, const int* in_sizes, int n_in,
                              void* d_out, int out_size)
{
    const float* q  = (const float*)d_in[0];
    const float* k  = (const float*)d_in[1];
    const float* v  = (const float*)d_in[2];
    const float* tm = (const float*)d_in[3];
    const float* am = (const float*)d_in[4];
    const float* wq = (const float*)d_in[6];
    const float* bq = (const float*)d_in[7];
    const float* wk = (const float*)d_in[8];
    const float* bk = (const float*)d_in[9];
    const float* wv = (const float*)d_in[10];
    const float* bv = (const float*)d_in[11];
    const float* wo = (const float*)d_in[12];
    const float* bo = (const float*)d_in[13];
    float* out = (float*)d_out;

    __half *xq, *xk, *xv, *wh, *gq, *gk, *gv, *gattn;
    float *gcoef;
    cudaGetSymbolAddress((void**)&xq,    g_xq);
    cudaGetSymbolAddress((void**)&xk,    g_xk);
    cudaGetSymbolAddress((void**)&xv,    g_xv);
    cudaGetSymbolAddress((void**)&wh,    g_wh);
    cudaGetSymbolAddress((void**)&gq,    g_qh);
    cudaGetSymbolAddress((void**)&gk,    g_kh);
    cudaGetSymbolAddress((void**)&gv,    g_vh);
    cudaGetSymbolAddress((void**)&gattn, g_attnh);
    cudaGetSymbolAddress((void**)&gcoef, g_coef);

    cudaFuncSetAttribute(gemm_qkv, cudaFuncAttributeMaxDynamicSharedMemorySize, GEMM_SMEM);
    cudaFuncSetAttribute(gemm_out, cudaFuncAttributeMaxDynamicSharedMemorySize, GEMM_SMEM);
    cudaFuncSetAttribute(attn_kernel, cudaFuncAttributeMaxDynamicSharedMemorySize, ATTN_SMEM);

    const int NBIG = BB*LL*DMODEL/4;
    const int NW   = WSZ/4;
    CvtArgs ca;
    ca.src[0] = q;  ca.dst[0] = xq;         ca.n4[0] = NBIG;
    ca.src[1] = k;  ca.dst[1] = xk;         ca.n4[1] = NBIG;
    ca.src[2] = v;  ca.dst[2] = xv;         ca.n4[2] = NBIG;
    ca.src[3] = wq; ca.dst[3] = wh;         ca.n4[3] = NW;
    ca.src[4] = wk; ca.dst[4] = wh + WSZ;   ca.n4[4] = NW;
    ca.src[5] = wv; ca.dst[5] = wh + 2*WSZ; ca.n4[5] = NW;
    ca.src[6] = wo; ca.dst[6] = wh + 3*WSZ; ca.n4[6] = NW;
    cvt_kernel<<<dim3(256, 7), 256>>>(ca);

    coef_kernel<<<2, 1024>>>(tm, am);

    QkvArgs qkv;
    qkv.X[0] = xq; qkv.X[1] = xk; qkv.X[2] = xv;
    qkv.W[0] = wh; qkv.W[1] = wh + WSZ; qkv.W[2] = wh + 2*WSZ;
    qkv.bias[0] = bq; qkv.bias[1] = bk; qkv.bias[2] = bv;
    qkv.Y[0] = gq; qkv.Y[1] = gk; qkv.Y[2] = gv;
    qkv.mode[0] = 1; qkv.mode[1] = 2; qkv.mode[2] = 3;
    qkv.coef = gcoef;
    gemm_qkv<<<dim3(8, 32, 3), 256, GEMM_SMEM>>>(qkv);

    attn_kernel<<<dim3(16, 16), 256, ATTN_SMEM>>>();

    gemm_out<<<dim3(8, 32), 256, GEMM_SMEM>>>(gattn, wh + 3*WSZ, bo, out);
}

// round 15
// speedup vs baseline: 1.4040x; 1.0003x over previous
#include <cuda_runtime.h>
#include <cuda_fp16.h>
#include <cstdint>

#define BB     2
#define LL     2048
#define LTXT   1024
#define DMODEL 512
#define NHEAD  8
#define DHEAD  64
#define WSZ    (DMODEL*DMODEL)

// Scratch (device globals; no allocations allowed)
__device__ __half g_xq[BB*LL*DMODEL];
__device__ __half g_xk[BB*LL*DMODEL];
__device__ __half g_xv[BB*LL*DMODEL];
__device__ __half g_wh[4*WSZ];
__device__ __half g_qh[BB*NHEAD*LL*DHEAD];    // [bh][l][d], pre-scaled log2e/8
__device__ __half g_kh[BB*NHEAD*LL*DHEAD];    // [bh][l][d]
__device__ __half g_vh[BB*NHEAD*LL*DHEAD];    // TRANSPOSED [bh][d][l], pre-mul coef
__device__ __half g_attnh[BB*LL*DMODEL];      // [l][512]
__device__ float  g_coef[BB*LL];
__device__ __half g_kmulh[BB*LL];             // 1.0 (unmasked) or 0.0 (masked)

// ---------------------------------------------------------------------------
// Helpers
// ---------------------------------------------------------------------------
__device__ __forceinline__ uint32_t pk(float lo, float hi) {
    __half2 h = __floats2half2_rn(lo, hi);
    return *reinterpret_cast<uint32_t*>(&h);
}
__device__ __forceinline__ uint32_t pkcvt(float lo, float hi) {
    uint32_t r;
    asm("cvt.rn.f16x2.f32 %0, %1, %2;" : "=r"(r) : "f"(hi), "f"(lo));
    return r;
}
__device__ __forceinline__ uint32_t h2ex2(uint32_t x) {
    uint32_t r;
    asm("ex2.approx.f16x2 %0, %1;" : "=r"(r) : "r"(x));
    return r;
}
__device__ __forceinline__ uint32_t h2mul(uint32_t a, uint32_t b) {
    uint32_t r;
    asm("mul.f16x2 %0, %1, %2;" : "=r"(r) : "r"(a), "r"(b));
    return r;
}
__device__ __forceinline__ float ex2(float x) {
    float r;
    asm("ex2.approx.f32 %0, %1;" : "=f"(r) : "f"(x));
    return r;
}
__device__ __forceinline__ void mma16(float* c,
    uint32_t a0, uint32_t a1, uint32_t a2, uint32_t a3,
    uint32_t b0, uint32_t b1)
{
    asm("mma.sync.aligned.m16n8k16.row.col.f32.f16.f16.f32 "
        "{%0,%1,%2,%3},{%4,%5,%6,%7},{%8,%9},{%0,%1,%2,%3};"
        : "+f"(c[0]), "+f"(c[1]), "+f"(c[2]), "+f"(c[3])
        : "r"(a0), "r"(a1), "r"(a2), "r"(a3), "r"(b0), "r"(b1));
}
__device__ __forceinline__ void ldsm4(uint32_t& r0, uint32_t& r1,
                                      uint32_t& r2, uint32_t& r3, uint32_t addr)
{
    asm volatile("ldmatrix.sync.aligned.m8n8.x4.shared.b16 {%0,%1,%2,%3}, [%4];"
        : "=r"(r0), "=r"(r1), "=r"(r2), "=r"(r3) : "r"(addr));
}
__device__ __forceinline__ void cp_async16(uint32_t saddr, const void* gptr) {
    asm volatile("cp.async.cg.shared.global [%0], [%1], 16;" :: "r"(saddr), "l"(gptr));
}
__device__ __forceinline__ void cp_commit() {
    asm volatile("cp.async.commit_group;");
}

// ---------------------------------------------------------------------------
// fp32 -> fp16 bulk convert (7 tensors)
// ---------------------------------------------------------------------------
struct CvtArgs {
    const float* src[7];
    __half*      dst[7];
    int          n4[7];
};

__global__ void __launch_bounds__(256) cvt_kernel(CvtArgs a)
{
    const int z = blockIdx.y;
    const float4* s = (const float4*)a.src[z];
    uint2* d = (uint2*)a.dst[z];
    const int n4 = a.n4[z];
    for (int i = blockIdx.x*256 + threadIdx.x; i < n4; i += gridDim.x*256) {
        float4 v = s[i];
        d[i] = make_uint2(pk(v.x, v.y), pk(v.z, v.w));
    }
}

// ---------------------------------------------------------------------------
// Mask -> coef (post-softmax weight; 0 iff masked) + multiplicative key mask.
// ---------------------------------------------------------------------------
__global__ void coef_kernel(const float* __restrict__ tm, const float* __restrict__ am)
{
    int b = blockIdx.x;
    int t = threadIdx.x;
    float tv = tm[b*LTXT + t];
    float av = am[b*LTXT + t];
    float ts = tv, as_ = av;
    #pragma unroll
    for (int o = 16; o; o >>= 1) {
        ts  += __shfl_xor_sync(0xffffffffu, ts,  o);
        as_ += __shfl_xor_sync(0xffffffffu, as_, o);
    }
    __shared__ float st[32], sa[32];
    int warp = t >> 5, lane = t & 31;
    if (lane == 0) { st[warp] = ts; sa[warp] = as_; }
    __syncthreads();
    if (warp == 0) {
        ts = st[lane]; as_ = sa[lane];
        #pragma unroll
        for (int o = 16; o; o >>= 1) {
            ts  += __shfl_xor_sync(0xffffffffu, ts,  o);
            as_ += __shfl_xor_sync(0xffffffffu, as_, o);
        }
        if (lane == 0) { st[0] = ts; sa[0] = as_; }
    }
    __syncthreads();
    float tsum = st[0], asum = sa[0], tot = tsum + asum;
    g_coef[b*LL + t]         = tv * (tot / (2.0f * tsum));
    g_coef[b*LL + LTXT + t]  = av * (tot / (2.0f * asum));
    g_kmulh[b*LL + t]        = __float2half(tv == 0.0f ? 0.0f : 1.0f);
    g_kmulh[b*LL + LTXT + t] = __float2half(av == 0.0f ? 0.0f : 1.0f);
}

// ---------------------------------------------------------------------------
// FP16 TC GEMM, 2-stage cp.async (smem 55KB -> 3 CTAs/SM), BK=64,
// ldmatrix.x4 fragment loads.  (unchanged from R14)
// ---------------------------------------------------------------------------
#define GAP 36
#define XST (128*GAP)
#define WST (64*GAP)
#define GEMM_SMEM (2*(XST + WST)*4)
#define NKC (DMODEL/64)

struct QkvArgs {
    const __half* X[3];
    const __half* W[3];
    const float*  bias[3];
    __half*       Y[3];
    int           mode[3];
    const float*  coef;
};

template<typename EPI>
__device__ __forceinline__ void gemm_core(
    const __half* __restrict__ X, const __half* __restrict__ W,
    uint32_t* smem, int m0, int n0, EPI epi)
{
    uint32_t* sX = smem;
    uint32_t* sW = smem + 2*XST;

    const int tid  = threadIdx.x;
    const int warp = tid >> 5, lane = tid & 31;
    const int wm = (warp >> 1) * 32;
    const int wn = (warp & 1) * 32;
    const int rowin = lane & 7;
    const int selh  = lane >> 4;
    const int sell  = (lane >> 3) & 1;

    const uint32_t bX = (uint32_t)__cvta_generic_to_shared(sX);
    const uint32_t bW = (uint32_t)__cvta_generic_to_shared(sW);

    auto prefetch = [&](int buf, int k0) {
        #pragma unroll
        for (int i = 0; i < 4; i++) {
            int s = tid + i*256;
            int r = s >> 3, ch = s & 7;
            cp_async16(bX + (buf*XST + r*GAP + ch*4)*4,
                       X + (size_t)(m0 + r)*DMODEL + k0 + ch*8);
        }
        #pragma unroll
        for (int i = 0; i < 2; i++) {
            int s = tid + i*256;
            int r = s >> 3, ch = s & 7;
            cp_async16(bW + (buf*WST + r*GAP + ch*4)*4,
                       W + (size_t)(n0 + r)*DMODEL + k0 + ch*8);
        }
        cp_commit();
    };

    const uint32_t xoff = ((wm + sell*8 + rowin)*GAP + selh*4)*4;
    const uint32_t woff = ((wn + selh*8 + rowin)*GAP + sell*4)*4;

    float c[2][4][4] = {};

    prefetch(0, 0);
    #pragma unroll 1
    for (int kc = 0; kc < NKC; kc++) {
        asm volatile("cp.async.wait_group 0;");
        __syncthreads();
        if (kc + 1 < NKC) prefetch((kc+1) & 1, (kc+1)*64);

        const uint32_t xb = bX + (kc & 1)*XST*4 + xoff;
        const uint32_t wb = bW + (kc & 1)*WST*4 + woff;
        #pragma unroll
        for (int kk = 0; kk < 4; kk++) {
            uint32_t a[2][4];
            ldsm4(a[0][0], a[0][1], a[0][2], a[0][3], xb + kk*32);
            ldsm4(a[1][0], a[1][1], a[1][2], a[1][3], xb + 16*GAP*4 + kk*32);
            #pragma unroll
            for (int njp = 0; njp < 2; njp++) {
                uint32_t b0, b1, b2, b3;
                ldsm4(b0, b1, b2, b3, wb + njp*16*GAP*4 + kk*32);
                mma16(c[0][2*njp  ], a[0][0], a[0][1], a[0][2], a[0][3], b0, b1);
                mma16(c[1][2*njp  ], a[1][0], a[1][1], a[1][2], a[1][3], b0, b1);
                mma16(c[0][2*njp+1], a[0][0], a[0][1], a[0][2], a[0][3], b2, b3);
                mma16(c[1][2*njp+1], a[1][0], a[1][1], a[1][2], a[1][3], b2, b3);
            }
        }
    }

    const int qr = lane >> 2, qc = lane & 3;
    #pragma unroll
    for (int mi = 0; mi < 2; mi++) {
        int row0 = m0 + wm + mi*16 + qr;
        #pragma unroll
        for (int nj = 0; nj < 4; nj++) {
            int col = n0 + wn + nj*8 + qc*2;
            epi(row0, col, c[mi][nj]);
        }
    }
}

__global__ void __launch_bounds__(256, 3) gemm_qkv(QkvArgs args)
{
    extern __shared__ uint32_t smg[];
    const int z = blockIdx.z;
    const float* B = args.bias[z];
    __half* Y = args.Y[z];
    const int mode = args.mode[z];
    const float* coef = args.coef;

    gemm_core(args.X[z], args.W[z], smg, blockIdx.y*128, blockIdx.x*64,
        [&](int row0, int col, float* cc) {
            int row1 = row0 + 8;
            float b0 = B[col], b1 = B[col+1];
            float v00 = cc[0] + b0, v01 = cc[1] + b1;
            float v10 = cc[2] + b0, v11 = cc[3] + b1;
            int h = col >> 6, d = col & 63;
            int bi0 = row0 >> 11, l0 = row0 & 2047;
            int bi1 = row1 >> 11, l1 = row1 & 2047;
            if (mode == 1) {          // Q: 1/8 * log2(e)  (log2-domain softmax)
                const float qs = 0.125f * 1.44269504f;
                v00 *= qs; v01 *= qs; v10 *= qs; v11 *= qs;
            }
            if (mode == 3) {
                float c0 = coef[row0], c1 = coef[row1];
                __half* p = Y + ((size_t)(bi0*NHEAD + h)*DHEAD + d)*LL;  // [bh][d][l]
                p[l0]      = __float2half(v00*c0);
                p[LL + l0] = __float2half(v01*c0);
                p[l1]      = __float2half(v10*c1);
                p[LL + l1] = __float2half(v11*c1);
            } else {
                *(__half2*)(Y + ((size_t)(bi0*NHEAD + h)*LL + l0)*DHEAD + d) =
                    __floats2half2_rn(v00, v01);
                *(__half2*)(Y + ((size_t)(bi1*NHEAD + h)*LL + l1)*DHEAD + d) =
                    __floats2half2_rn(v10, v11);
            }
        });
}

__global__ void __launch_bounds__(256, 3) gemm_out(
    const __half* __restrict__ Xh, const __half* __restrict__ Wh,
    const float* __restrict__ B, float* __restrict__ Y)
{
    extern __shared__ uint32_t smg[];
    gemm_core(Xh, Wh, smg, blockIdx.y*128, blockIdx.x*64,
        [&](int row0, int col, float* cc) {
            float b0 = B[col], b1 = B[col+1];
            *(float2*)(Y + (size_t)row0*DMODEL + col)     = make_float2(cc[0]+b0, cc[1]+b1);
            *(float2*)(Y + (size_t)(row0+8)*DMODEL + col) = make_float2(cc[2]+b0, cc[3]+b1);
        });
}

// ---------------------------------------------------------------------------
// Fused attention v8: 4 K/V buffers, ONE barrier per PAIR of tiles.
// Warps skew freely across the pair -> cross-warp mma fills softmax bubbles.
// fp16 m16n8k16 + ldmatrix.x4, log2 softmax, l-via-mma, mult. key mask.
// ---------------------------------------------------------------------------
#define AP 36
#define KT (64*AP)
#define MB 32
#define ATTN_SMEM ((8*KT + 4*MB) * 4)
#define NT (LL/64)

__global__ void __launch_bounds__(256, 2) attn_kernel()
{
    extern __shared__ uint32_t smu[];
    uint32_t* Ks  = smu;                    // [4][64key][AP]
    uint32_t* Vs  = smu + 4*KT;             // [4][64d][AP]  (V^T)
    uint32_t* kms = smu + 8*KT;             // [4][MB] half2 key mask

    const int tid  = threadIdx.x;
    const int warp = tid >> 5, lane = tid & 31;
    const int qr = lane >> 2, qc = lane & 3;
    const int bh = blockIdx.y, bi = bh >> 3, h = bh & 7;
    const int q0 = blockIdx.x * 128;
    const int wrow = warp * 16;
    const int rowin = lane & 7;
    const int selh  = lane >> 4;
    const int sell  = (lane >> 3) & 1;

    const __half* kbase = g_kh + (size_t)bh * LL * DHEAD;
    const __half* vbase = g_vh + (size_t)bh * DHEAD * LL;
    const float*  cbase = g_coef + bi*LL;
    const __half* mbase = g_kmulh + bi*LL;

    const uint32_t sK = (uint32_t)__cvta_generic_to_shared(Ks);
    const uint32_t sV = (uint32_t)__cvta_generic_to_shared(Vs);
    const uint32_t sM = (uint32_t)__cvta_generic_to_shared(kms);

    auto prefetch = [&](int buf, int k0) {
        #pragma unroll
        for (int i = 0; i < 2; i++) {
            int s = tid + i*256;
            int r = s >> 3, ch = s & 7;
            cp_async16(sK + (buf*KT + r*AP + ch*4)*4,
                       kbase + (size_t)(k0 + r)*DHEAD + ch*8);
            cp_async16(sV + (buf*KT + r*AP + ch*4)*4,
                       vbase + (size_t)r*LL + k0 + ch*8);
        }
        if (tid < 8)
            cp_async16(sM + (buf*MB + tid*4)*4, mbase + k0 + tid*8);
        cp_commit();
    };

    prefetch(0, 0);
    prefetch(1, 64);

    // ---- Q fragments straight from gmem (fp16, pre-scaled log2e/8) ----
    const uint32_t* qrow0 =
        (const uint32_t*)(g_qh + ((size_t)bh*LL + q0 + wrow + qr)*DHEAD);
    const uint32_t* qrow1 = qrow0 + 8*(DHEAD/2);
    uint32_t aQ[4][4];
    #pragma unroll
    for (int kk = 0; kk < 4; kk++) {
        aQ[kk][0] = qrow0[kk*8 + qc];
        aQ[kk][1] = qrow1[kk*8 + qc];
        aQ[kk][2] = qrow0[kk*8 + qc + 4];
        aQ[kk][3] = qrow1[kk*8 + qc + 4];
    }
    const bool q0ok = (cbase[q0 + wrow + qr]     != 0.0f);
    const bool q1ok = (cbase[q0 + wrow + qr + 8] != 0.0f);

    const uint32_t fragoff = (((selh*8 + rowin)*AP) + sell*4)*4;
    const uint32_t bOnes = (qr == 0) ? 0x3C003C00u : 0u;

    float o[8][4] = {};
    float ol[4] = {};
    float m0 = -1e30f, m1 = -1e30f;

    #pragma unroll 1
    for (int p = 0; p < NT; p += 2) {
        asm volatile("cp.async.wait_group 0;");   // tiles p, p+1 landed
        __syncthreads();                          // pair p-2 reads all finished
        if (p + 2 < NT) {
            prefetch((p+2) & 3, (p+2)*64);        // buffers of pair p-2 (safe)
            prefetch((p+3) & 3, (p+3)*64);
        }

        #pragma unroll
        for (int u = 0; u < 2; u++) {
            const int buf = (p + u) & 3;
            const uint32_t kb_a = sK + buf*KT*4 + fragoff;
            const uint32_t vb_a = sV + buf*KT*4 + fragoff;
            const uint32_t* km  = kms + buf*MB;

            // ---- S = (Q·log2e/8) @ K^T ----
            float s[8][4] = {};
            #pragma unroll
            for (int kk = 0; kk < 4; kk++) {
                #pragma unroll
                for (int jp = 0; jp < 4; jp++) {
                    uint32_t b0, b1, b2, b3;
                    ldsm4(b0, b1, b2, b3, kb_a + (jp*16*AP)*4 + kk*32);
                    mma16(s[2*jp  ], aQ[kk][0], aQ[kk][1], aQ[kk][2], aQ[kk][3], b0, b1);
                    mma16(s[2*jp+1], aQ[kk][0], aQ[kk][1], aQ[kk][2], aQ[kk][3], b2, b3);
                }
            }

            // ---- q-masked rows -> 0 (uniform softmax, l=2048) ----
            if (!q0ok) {
                #pragma unroll
                for (int j = 0; j < 8; j++) { s[j][0] = 0.0f; s[j][1] = 0.0f; }
            }
            if (!q1ok) {
                #pragma unroll
                for (int j = 0; j < 8; j++) { s[j][2] = 0.0f; s[j][3] = 0.0f; }
            }

            // ---- online softmax max ----
            float mx0 = -1e30f, mx1 = -1e30f;
            #pragma unroll
            for (int j = 0; j < 8; j++) {
                mx0 = fmaxf(mx0, fmaxf(s[j][0], s[j][1]));
                mx1 = fmaxf(mx1, fmaxf(s[j][2], s[j][3]));
            }
            mx0 = fmaxf(mx0, __shfl_xor_sync(0xffffffffu, mx0, 1));
            mx0 = fmaxf(mx0, __shfl_xor_sync(0xffffffffu, mx0, 2));
            mx1 = fmaxf(mx1, __shfl_xor_sync(0xffffffffu, mx1, 1));
            mx1 = fmaxf(mx1, __shfl_xor_sync(0xffffffffu, mx1, 2));

            if (__any_sync(0xffffffffu, (mx0 > m0) | (mx1 > m1))) {
                float nm0 = fmaxf(m0, mx0), nm1 = fmaxf(m1, mx1);
                float sc0 = ex2(m0 - nm0), sc1 = ex2(m1 - nm1);
                #pragma unroll
                for (int j = 0; j < 8; j++) {
                    o[j][0] *= sc0; o[j][1] *= sc0;
                    o[j][2] *= sc1; o[j][3] *= sc1;
                }
                ol[0] *= sc0; ol[1] *= sc0;
                ol[2] *= sc1; ol[3] *= sc1;
                m0 = nm0;  m1 = nm1;
            }

            // ---- exp2 (f16x2) -> masked A-frags -> PV mma + l-mma ----
            #pragma unroll
            for (int jj = 0; jj < 4; jj++) {
                uint32_t a0 = h2ex2(pkcvt(s[2*jj  ][0] - m0, s[2*jj  ][1] - m0));
                uint32_t a1 = h2ex2(pkcvt(s[2*jj  ][2] - m1, s[2*jj  ][3] - m1));
                uint32_t a2 = h2ex2(pkcvt(s[2*jj+1][0] - m0, s[2*jj+1][1] - m0));
                uint32_t a3 = h2ex2(pkcvt(s[2*jj+1][2] - m1, s[2*jj+1][3] - m1));

                uint32_t km_e = km[(2*jj  )*4 + qc];
                uint32_t km_o = km[(2*jj+1)*4 + qc];
                if (q0ok) { a0 = h2mul(a0, km_e); a2 = h2mul(a2, km_o); }
                if (q1ok) { a1 = h2mul(a1, km_e); a3 = h2mul(a3, km_o); }

                #pragma unroll
                for (int njp = 0; njp < 4; njp++) {
                    uint32_t b0, b1, b2, b3;
                    ldsm4(b0, b1, b2, b3, vb_a + (njp*16*AP)*4 + jj*32);
                    mma16(o[2*njp  ], a0, a1, a2, a3, b0, b1);
                    mma16(o[2*njp+1], a0, a1, a2, a3, b2, b3);
                }
                mma16(ol, a0, a1, a2, a3, bOnes, bOnes);
            }
        }
    }

    // ---- epilogue: recover l from qc==0 lanes, normalize, write fp16 ----
    float lq0 = __shfl_sync(0xffffffffu, ol[0], lane & ~3);
    float lq1 = __shfl_sync(0xffffffffu, ol[2], lane & ~3);
    float inv0 = 1.0f / lq0, inv1 = 1.0f / lq1;
    int r0 = q0 + wrow + qr, r1 = r0 + 8;
    #pragma unroll
    for (int j = 0; j < 8; j++) {
        int d = h*64 + j*8 + qc*2;
        *(__half2*)(g_attnh + ((size_t)(bi*LL + r0))*DMODEL + d) =
            __floats2half2_rn(o[j][0]*inv0, o[j][1]*inv0);
        *(__half2*)(g_attnh + ((size_t)(bi*LL + r1))*DMODEL + d) =
            __floats2half2_rn(o[j][2]*inv1, o[j][3]*inv1);
    }
}

// ---------------------------------------------------------------------------
extern "C" void kernel_launch(void* const* d_in, const int* in_sizes, int n_in,
                              void* d_out, int out_size)
{
    const float* q  = (const float*)d_in[0];
    const float* k  = (const float*)d_in[1];
    const float* v  = (const float*)d_in[2];
    const float* tm = (const float*)d_in[3];
    const float* am = (const float*)d_in[4];
    const float* wq = (const float*)d_in[6];
    const float* bq = (const float*)d_in[7];
    const float* wk = (const float*)d_in[8];
    const float* bk = (const float*)d_in[9];
    const float* wv = (const float*)d_in[10];
    const float* bv = (const float*)d_in[11];
    const float* wo = (const float*)d_in[12];
    const float* bo = (const float*)d_in[13];
    float* out = (float*)d_out;

    __half *xq, *xk, *xv, *wh, *gq, *gk, *gv, *gattn;
    float *gcoef;
    cudaGetSymbolAddress((void**)&xq,    g_xq);
    cudaGetSymbolAddress((void**)&xk,    g_xk);
    cudaGetSymbolAddress((void**)&xv,    g_xv);
    cudaGetSymbolAddress((void**)&wh,    g_wh);
    cudaGetSymbolAddress((void**)&gq,    g_qh);
    cudaGetSymbolAddress((void**)&gk,    g_kh);
    cudaGetSymbolAddress((void**)&gv,    g_vh);
    cudaGetSymbolAddress((void**)&gattn, g_attnh);
    cudaGetSymbolAddress((void**)&gcoef, g_coef);

    cudaFuncSetAttribute(gemm_qkv, cudaFuncAttributeMaxDynamicSharedMemorySize, GEMM_SMEM);
    cudaFuncSetAttribute(gemm_out, cudaFuncAttributeMaxDynamicSharedMemorySize, GEMM_SMEM);
    cudaFuncSetAttribute(attn_kernel, cudaFuncAttributeMaxDynamicSharedMemorySize, ATTN_SMEM);

    const int NBIG = BB*LL*DMODEL/4;
    const int NW   = WSZ/4;
    CvtArgs ca;
    ca.src[0] = q;  ca.dst[0] = xq;         ca.n4[0] = NBIG;
    ca.src[1] = k;  ca.dst[1] = xk;         ca.n4[1] = NBIG;
    ca.src[2] = v;  ca.dst[2] = xv;         ca.n4[2] = NBIG;
    ca.src[3] = wq; ca.dst[3] = wh;         ca.n4[3] = NW;
    ca.src[4] = wk; ca.dst[4] = wh + WSZ;   ca.n4[4] = NW;
    ca.src[5] = wv; ca.dst[5] = wh + 2*WSZ; ca.n4[5] = NW;
    ca.src[6] = wo; ca.dst[6] = wh + 3*WSZ; ca.n4[6] = NW;
    cvt_kernel<<<dim3(256, 7), 256>>>(ca);

    coef_kernel<<<2, 1024>>>(tm, am);

    QkvArgs qkv;
    qkv.X[0] = xq; qkv.X[1] = xk; qkv.X[2] = xv;
    qkv.W[0] = wh; qkv.W[1] = wh + WSZ; qkv.W[2] = wh + 2*WSZ;
    qkv.bias[0] = bq; qkv.bias[1] = bk; qkv.bias[2] = bv;
    qkv.Y[0] = gq; qkv.Y[1] = gk; qkv.Y[2] = gv;
    qkv.mode[0] = 1; qkv.mode[1] = 2; qkv.mode[2] = 3;
    qkv.coef = gcoef;
    gemm_qkv<<<dim3(8, 32, 3), 256, GEMM_SMEM>>>(qkv);

    attn_kernel<<<dim3(16, 16), 256, ATTN_SMEM>>>();

    gemm_out<<<dim3(8, 32), 256, GEMM_SMEM>>>(gattn, wh + 3*WSZ, bo, out);
}

// round 17
// speedup vs baseline: 1.4734x; 1.0495x over previous
#include <cuda_runtime.h>
#include <cuda_fp16.h>
#include <cstdint>

#define BB     2
#define LL     2048
#define LTXT   1024
#define DMODEL 512
#define NHEAD  8
#define DHEAD  64
#define WSZ    (DMODEL*DMODEL)

// Scratch (device globals; no allocations allowed)
__device__ __half g_xq[BB*LL*DMODEL];
__device__ __half g_xk[BB*LL*DMODEL];
__device__ __half g_xv[BB*LL*DMODEL];
__device__ __half g_wh[4*WSZ];
__device__ __half g_qh[BB*NHEAD*LL*DHEAD];    // [bh][l][d], pre-scaled log2e/8
__device__ __half g_kh[BB*NHEAD*LL*DHEAD];    // [bh][l][d]
__device__ __half g_vh[BB*NHEAD*LL*DHEAD];    // TRANSPOSED [bh][d][l], pre-mul coef
__device__ __half g_attnh[BB*LL*DMODEL];      // [l][512]
__device__ float  g_coef[BB*LL];
__device__ __half g_kmulh[BB*LL];             // 1.0 (unmasked) or 0.0 (masked)

// ---------------------------------------------------------------------------
// Helpers
// ---------------------------------------------------------------------------
__device__ __forceinline__ uint32_t pk(float lo, float hi) {
    __half2 h = __floats2half2_rn(lo, hi);
    return *reinterpret_cast<uint32_t*>(&h);
}
__device__ __forceinline__ uint32_t h2mul(uint32_t a, uint32_t b) {
    uint32_t r;
    asm("mul.f16x2 %0, %1, %2;" : "=r"(r) : "r"(a), "r"(b));
    return r;
}
__device__ __forceinline__ float ex2(float x) {
    float r;
    asm("ex2.approx.f32 %0, %1;" : "=f"(r) : "f"(x));
    return r;
}
__device__ __forceinline__ void mma16(float* c,
    uint32_t a0, uint32_t a1, uint32_t a2, uint32_t a3,
    uint32_t b0, uint32_t b1)
{
    asm("mma.sync.aligned.m16n8k16.row.col.f32.f16.f16.f32 "
        "{%0,%1,%2,%3},{%4,%5,%6,%7},{%8,%9},{%0,%1,%2,%3};"
        : "+f"(c[0]), "+f"(c[1]), "+f"(c[2]), "+f"(c[3])
        : "r"(a0), "r"(a1), "r"(a2), "r"(a3), "r"(b0), "r"(b1));
}
__device__ __forceinline__ void ldsm4(uint32_t& r0, uint32_t& r1,
                                      uint32_t& r2, uint32_t& r3, uint32_t addr)
{
    asm volatile("ldmatrix.sync.aligned.m8n8.x4.shared.b16 {%0,%1,%2,%3}, [%4];"
        : "=r"(r0), "=r"(r1), "=r"(r2), "=r"(r3) : "r"(addr));
}
__device__ __forceinline__ void cp_async16(uint32_t saddr, const void* gptr) {
    asm volatile("cp.async.cg.shared.global [%0], [%1], 16;" :: "r"(saddr), "l"(gptr));
}
__device__ __forceinline__ void cp_commit() {
    asm volatile("cp.async.commit_group;");
}

// ---------------------------------------------------------------------------
// fp32 -> fp16 bulk convert (7 tensors)
// ---------------------------------------------------------------------------
struct CvtArgs {
    const float* src[7];
    __half*      dst[7];
    int          n4[7];
};

__global__ void __launch_bounds__(256) cvt_kernel(CvtArgs a)
{
    const int z = blockIdx.y;
    const float4* s = (const float4*)a.src[z];
    uint2* d = (uint2*)a.dst[z];
    const int n4 = a.n4[z];
    for (int i = blockIdx.x*256 + threadIdx.x; i < n4; i += gridDim.x*256) {
        float4 v = s[i];
        d[i] = make_uint2(pk(v.x, v.y), pk(v.z, v.w));
    }
}

// ---------------------------------------------------------------------------
// Mask -> coef (post-softmax weight; 0 iff masked) + multiplicative key mask.
// ---------------------------------------------------------------------------
__global__ void coef_kernel(const float* __restrict__ tm, const float* __restrict__ am)
{
    int b = blockIdx.x;
    int t = threadIdx.x;
    float tv = tm[b*LTXT + t];
    float av = am[b*LTXT + t];
    float ts = tv, as_ = av;
    #pragma unroll
    for (int o = 16; o; o >>= 1) {
        ts  += __shfl_xor_sync(0xffffffffu, ts,  o);
        as_ += __shfl_xor_sync(0xffffffffu, as_, o);
    }
    __shared__ float st[32], sa[32];
    int warp = t >> 5, lane = t & 31;
    if (lane == 0) { st[warp] = ts; sa[warp] = as_; }
    __syncthreads();
    if (warp == 0) {
        ts = st[lane]; as_ = sa[lane];
        #pragma unroll
        for (int o = 16; o; o >>= 1) {
            ts  += __shfl_xor_sync(0xffffffffu, ts,  o);
            as_ += __shfl_xor_sync(0xffffffffu, as_, o);
        }
        if (lane == 0) { st[0] = ts; sa[0] = as_; }
    }
    __syncthreads();
    float tsum = st[0], asum = sa[0], tot = tsum + asum;
    g_coef[b*LL + t]         = tv * (tot / (2.0f * tsum));
    g_coef[b*LL + LTXT + t]  = av * (tot / (2.0f * asum));
    g_kmulh[b*LL + t]        = __float2half(tv == 0.0f ? 0.0f : 1.0f);
    g_kmulh[b*LL + LTXT + t] = __float2half(av == 0.0f ? 0.0f : 1.0f);
}

// ---------------------------------------------------------------------------
// FP16 TC GEMM, 2-stage cp.async (smem 55KB -> 3 CTAs/SM), BK=64,
// ldmatrix.x4 fragment loads.  (unchanged from R14)
// ---------------------------------------------------------------------------
#define GAP 36
#define XST (128*GAP)
#define WST (64*GAP)
#define GEMM_SMEM (2*(XST + WST)*4)
#define NKC (DMODEL/64)

struct QkvArgs {
    const __half* X[3];
    const __half* W[3];
    const float*  bias[3];
    __half*       Y[3];
    int           mode[3];
    const float*  coef;
};

template<typename EPI>
__device__ __forceinline__ void gemm_core(
    const __half* __restrict__ X, const __half* __restrict__ W,
    uint32_t* smem, int m0, int n0, EPI epi)
{
    uint32_t* sX = smem;
    uint32_t* sW = smem + 2*XST;

    const int tid  = threadIdx.x;
    const int warp = tid >> 5, lane = tid & 31;
    const int wm = (warp >> 1) * 32;
    const int wn = (warp & 1) * 32;
    const int rowin = lane & 7;
    const int selh  = lane >> 4;
    const int sell  = (lane >> 3) & 1;

    const uint32_t bX = (uint32_t)__cvta_generic_to_shared(sX);
    const uint32_t bW = (uint32_t)__cvta_generic_to_shared(sW);

    auto prefetch = [&](int buf, int k0) {
        #pragma unroll
        for (int i = 0; i < 4; i++) {
            int s = tid + i*256;
            int r = s >> 3, ch = s & 7;
            cp_async16(bX + (buf*XST + r*GAP + ch*4)*4,
                       X + (size_t)(m0 + r)*DMODEL + k0 + ch*8);
        }
        #pragma unroll
        for (int i = 0; i < 2; i++) {
            int s = tid + i*256;
            int r = s >> 3, ch = s & 7;
            cp_async16(bW + (buf*WST + r*GAP + ch*4)*4,
                       W + (size_t)(n0 + r)*DMODEL + k0 + ch*8);
        }
        cp_commit();
    };

    const uint32_t xoff = ((wm + sell*8 + rowin)*GAP + selh*4)*4;
    const uint32_t woff = ((wn + selh*8 + rowin)*GAP + sell*4)*4;

    float c[2][4][4] = {};

    prefetch(0, 0);
    #pragma unroll 1
    for (int kc = 0; kc < NKC; kc++) {
        asm volatile("cp.async.wait_group 0;");
        __syncthreads();
        if (kc + 1 < NKC) prefetch((kc+1) & 1, (kc+1)*64);

        const uint32_t xb = bX + (kc & 1)*XST*4 + xoff;
        const uint32_t wb = bW + (kc & 1)*WST*4 + woff;
        #pragma unroll
        for (int kk = 0; kk < 4; kk++) {
            uint32_t a[2][4];
            ldsm4(a[0][0], a[0][1], a[0][2], a[0][3], xb + kk*32);
            ldsm4(a[1][0], a[1][1], a[1][2], a[1][3], xb + 16*GAP*4 + kk*32);
            #pragma unroll
            for (int njp = 0; njp < 2; njp++) {
                uint32_t b0, b1, b2, b3;
                ldsm4(b0, b1, b2, b3, wb + njp*16*GAP*4 + kk*32);
                mma16(c[0][2*njp  ], a[0][0], a[0][1], a[0][2], a[0][3], b0, b1);
                mma16(c[1][2*njp  ], a[1][0], a[1][1], a[1][2], a[1][3], b0, b1);
                mma16(c[0][2*njp+1], a[0][0], a[0][1], a[0][2], a[0][3], b2, b3);
                mma16(c[1][2*njp+1], a[1][0], a[1][1], a[1][2], a[1][3], b2, b3);
            }
        }
    }

    const int qr = lane >> 2, qc = lane & 3;
    #pragma unroll
    for (int mi = 0; mi < 2; mi++) {
        int row0 = m0 + wm + mi*16 + qr;
        #pragma unroll
        for (int nj = 0; nj < 4; nj++) {
            int col = n0 + wn + nj*8 + qc*2;
            epi(row0, col, c[mi][nj]);
        }
    }
}

__global__ void __launch_bounds__(256, 3) gemm_qkv(QkvArgs args)
{
    extern __shared__ uint32_t smg[];
    const int z = blockIdx.z;
    const float* B = args.bias[z];
    __half* Y = args.Y[z];
    const int mode = args.mode[z];
    const float* coef = args.coef;

    gemm_core(args.X[z], args.W[z], smg, blockIdx.y*128, blockIdx.x*64,
        [&](int row0, int col, float* cc) {
            int row1 = row0 + 8;
            float b0 = B[col], b1 = B[col+1];
            float v00 = cc[0] + b0, v01 = cc[1] + b1;
            float v10 = cc[2] + b0, v11 = cc[3] + b1;
            int h = col >> 6, d = col & 63;
            int bi0 = row0 >> 11, l0 = row0 & 2047;
            int bi1 = row1 >> 11, l1 = row1 & 2047;
            if (mode == 1) {          // Q: 1/8 * log2(e)  (log2-domain softmax)
                const float qs = 0.125f * 1.44269504f;
                v00 *= qs; v01 *= qs; v10 *= qs; v11 *= qs;
            }
            if (mode == 3) {
                float c0 = coef[row0], c1 = coef[row1];
                __half* p = Y + ((size_t)(bi0*NHEAD + h)*DHEAD + d)*LL;  // [bh][d][l]
                p[l0]      = __float2half(v00*c0);
                p[LL + l0] = __float2half(v01*c0);
                p[l1]      = __float2half(v10*c1);
                p[LL + l1] = __float2half(v11*c1);
            } else {
                *(__half2*)(Y + ((size_t)(bi0*NHEAD + h)*LL + l0)*DHEAD + d) =
                    __floats2half2_rn(v00, v01);
                *(__half2*)(Y + ((size_t)(bi1*NHEAD + h)*LL + l1)*DHEAD + d) =
                    __floats2half2_rn(v10, v11);
            }
        });
}

__global__ void __launch_bounds__(256, 3) gemm_out(
    const __half* __restrict__ Xh, const __half* __restrict__ Wh,
    const float* __restrict__ B, float* __restrict__ Y)
{
    extern __shared__ uint32_t smg[];
    gemm_core(Xh, Wh, smg, blockIdx.y*128, blockIdx.x*64,
        [&](int row0, int col, float* cc) {
            float b0 = B[col], b1 = B[col+1];
            *(float2*)(Y + (size_t)row0*DMODEL + col)     = make_float2(cc[0]+b0, cc[1]+b1);
            *(float2*)(Y + (size_t)(row0+8)*DMODEL + col) = make_float2(cc[2]+b0, cc[3]+b1);
        });
}

// ---------------------------------------------------------------------------
// Fused attention v10: fixed-base softmax, base=0, f32 ex2.
// No running max, no shuffles, no rescale.  p = ex2(s) computed in f32
// (precise exponent), packed to fp16 (all significant p in normal range).
// 4 K/V buffers, one barrier per tile pair.  fp16 m16n8k16 + ldmatrix.x4.
// ---------------------------------------------------------------------------
#define AP 36
#define KT (64*AP)
#define MB 32
#define ATTN_SMEM ((8*KT + 4*MB) * 4)
#define NT (LL/64)

__global__ void __launch_bounds__(256, 2) attn_kernel()
{
    extern __shared__ uint32_t smu[];
    uint32_t* Ks  = smu;                    // [4][64key][AP]
    uint32_t* Vs  = smu + 4*KT;             // [4][64d][AP]  (V^T)
    uint32_t* kms = smu + 8*KT;             // [4][MB] half2 key mask

    const int tid  = threadIdx.x;
    const int warp = tid >> 5, lane = tid & 31;
    const int qr = lane >> 2, qc = lane & 3;
    const int bh = blockIdx.y, bi = bh >> 3, h = bh & 7;
    const int q0 = blockIdx.x * 128;
    const int wrow = warp * 16;
    const int rowin = lane & 7;
    const int selh  = lane >> 4;
    const int sell  = (lane >> 3) & 1;

    const __half* kbase = g_kh + (size_t)bh * LL * DHEAD;
    const __half* vbase = g_vh + (size_t)bh * DHEAD * LL;
    const float*  cbase = g_coef + bi*LL;
    const __half* mbase = g_kmulh + bi*LL;

    const uint32_t sK = (uint32_t)__cvta_generic_to_shared(Ks);
    const uint32_t sV = (uint32_t)__cvta_generic_to_shared(Vs);
    const uint32_t sM = (uint32_t)__cvta_generic_to_shared(kms);

    auto prefetch = [&](int buf, int k0) {
        #pragma unroll
        for (int i = 0; i < 2; i++) {
            int s = tid + i*256;
            int r = s >> 3, ch = s & 7;
            cp_async16(sK + (buf*KT + r*AP + ch*4)*4,
                       kbase + (size_t)(k0 + r)*DHEAD + ch*8);
            cp_async16(sV + (buf*KT + r*AP + ch*4)*4,
                       vbase + (size_t)r*LL + k0 + ch*8);
        }
        if (tid < 8)
            cp_async16(sM + (buf*MB + tid*4)*4, mbase + k0 + tid*8);
        cp_commit();
    };

    prefetch(0, 0);
    prefetch(1, 64);

    // ---- Q fragments straight from gmem (fp16, pre-scaled log2e/8) ----
    const uint32_t* qrow0 =
        (const uint32_t*)(g_qh + ((size_t)bh*LL + q0 + wrow + qr)*DHEAD);
    const uint32_t* qrow1 = qrow0 + 8*(DHEAD/2);
    uint32_t aQ[4][4];
    #pragma unroll
    for (int kk = 0; kk < 4; kk++) {
        aQ[kk][0] = qrow0[kk*8 + qc];
        aQ[kk][1] = qrow1[kk*8 + qc];
        aQ[kk][2] = qrow0[kk*8 + qc + 4];
        aQ[kk][3] = qrow1[kk*8 + qc + 4];
    }
    const bool q0ok = (cbase[q0 + wrow + qr]     != 0.0f);
    const bool q1ok = (cbase[q0 + wrow + qr + 8] != 0.0f);

    const uint32_t fragoff = (((selh*8 + rowin)*AP) + sell*4)*4;
    const uint32_t bOnes = (qr == 0) ? 0x3C003C00u : 0u;

    float o[8][4] = {};
    float ol[4] = {};

    #pragma unroll 1
    for (int p = 0; p < NT; p += 2) {
        asm volatile("cp.async.wait_group 0;");   // tiles p, p+1 landed
        __syncthreads();                          // pair p-2 reads all finished
        if (p + 2 < NT) {
            prefetch((p+2) & 3, (p+2)*64);
            prefetch((p+3) & 3, (p+3)*64);
        }

        #pragma unroll
        for (int u = 0; u < 2; u++) {
            const int buf = (p + u) & 3;
            const uint32_t kb_a = sK + buf*KT*4 + fragoff;
            const uint32_t vb_a = sV + buf*KT*4 + fragoff;
            const uint32_t* km  = kms + buf*MB;

            // ---- S = (Q·log2e/8) @ K^T ----
            float s[8][4] = {};
            #pragma unroll
            for (int kk = 0; kk < 4; kk++) {
                #pragma unroll
                for (int jp = 0; jp < 4; jp++) {
                    uint32_t b0, b1, b2, b3;
                    ldsm4(b0, b1, b2, b3, kb_a + (jp*16*AP)*4 + kk*32);
                    mma16(s[2*jp  ], aQ[kk][0], aQ[kk][1], aQ[kk][2], aQ[kk][3], b0, b1);
                    mma16(s[2*jp+1], aQ[kk][0], aQ[kk][1], aQ[kk][2], aQ[kk][3], b2, b3);
                }
            }

            // ---- q-masked rows -> uniform (p = 1 for all keys) ----
            if (!q0ok) {
                #pragma unroll
                for (int j = 0; j < 8; j++) { s[j][0] = 0.0f; s[j][1] = 0.0f; }
            }
            if (!q1ok) {
                #pragma unroll
                for (int j = 0; j < 8; j++) { s[j][2] = 0.0f; s[j][3] = 0.0f; }
            }

            // ---- f32 ex2 -> fp16 pack -> masked A-frags -> PV mma + l-mma ----
            #pragma unroll
            for (int jj = 0; jj < 4; jj++) {
                uint32_t a0 = pk(ex2(s[2*jj  ][0]), ex2(s[2*jj  ][1]));
                uint32_t a1 = pk(ex2(s[2*jj  ][2]), ex2(s[2*jj  ][3]));
                uint32_t a2 = pk(ex2(s[2*jj+1][0]), ex2(s[2*jj+1][1]));
                uint32_t a3 = pk(ex2(s[2*jj+1][2]), ex2(s[2*jj+1][3]));

                uint32_t km_e = km[(2*jj  )*4 + qc];
                uint32_t km_o = km[(2*jj+1)*4 + qc];
                if (q0ok) { a0 = h2mul(a0, km_e); a2 = h2mul(a2, km_o); }
                if (q1ok) { a1 = h2mul(a1, km_e); a3 = h2mul(a3, km_o); }

                #pragma unroll
                for (int njp = 0; njp < 4; njp++) {
                    uint32_t b0, b1, b2, b3;
                    ldsm4(b0, b1, b2, b3, vb_a + (njp*16*AP)*4 + jj*32);
                    mma16(o[2*njp  ], a0, a1, a2, a3, b0, b1);
                    mma16(o[2*njp+1], a0, a1, a2, a3, b2, b3);
                }
                mma16(ol, a0, a1, a2, a3, bOnes, bOnes);
            }
        }
    }

    // ---- epilogue: recover l from qc==0 lanes, normalize, write fp16 ----
    float lq0 = __shfl_sync(0xffffffffu, ol[0], lane & ~3);
    float lq1 = __shfl_sync(0xffffffffu, ol[2], lane & ~3);
    float inv0 = 1.0f / lq0, inv1 = 1.0f / lq1;
    int r0 = q0 + wrow + qr, r1 = r0 + 8;
    #pragma unroll
    for (int j = 0; j < 8; j++) {
        int d = h*64 + j*8 + qc*2;
        *(__half2*)(g_attnh + ((size_t)(bi*LL + r0))*DMODEL + d) =
            __floats2half2_rn(o[j][0]*inv0, o[j][1]*inv0);
        *(__half2*)(g_attnh + ((size_t)(bi*LL + r1))*DMODEL + d) =
            __floats2half2_rn(o[j][2]*inv1, o[j][3]*inv1);
    }
}

// ---------------------------------------------------------------------------
extern "C" void kernel_launch(void* const* d_in, const int* in_sizes, int n_in,
                              void* d_out, int out_size)
{
    const float* q  = (const float*)d_in[0];
    const float* k  = (const float*)d_in[1];
    const float* v  = (const float*)d_in[2];
    const float* tm = (const float*)d_in[3];
    const float* am = (const float*)d_in[4];
    const float* wq = (const float*)d_in[6];
    const float* bq = (const float*)d_in[7];
    const float* wk = (const float*)d_in[8];
    const float* bk = (const float*)d_in[9];
    const float* wv = (const float*)d_in[10];
    const float* bv = (const float*)d_in[11];
    const float* wo = (const float*)d_in[12];
    const float* bo = (const float*)d_in[13];
    float* out = (float*)d_out;

    __half *xq, *xk, *xv, *wh, *gq, *gk, *gv, *gattn;
    float *gcoef;
    cudaGetSymbolAddress((void**)&xq,    g_xq);
    cudaGetSymbolAddress((void**)&xk,    g_xk);
    cudaGetSymbolAddress((void**)&xv,    g_xv);
    cudaGetSymbolAddress((void**)&wh,    g_wh);
    cudaGetSymbolAddress((void**)&gq,    g_qh);
    cudaGetSymbolAddress((void**)&gk,    g_kh);
    cudaGetSymbolAddress((void**)&gv,    g_vh);
    cudaGetSymbolAddress((void**)&gattn, g_attnh);
    cudaGetSymbolAddress((void**)&gcoef, g_coef);

    cudaFuncSetAttribute(gemm_qkv, cudaFuncAttributeMaxDynamicSharedMemorySize, GEMM_SMEM);
    cudaFuncSetAttribute(gemm_out, cudaFuncAttributeMaxDynamicSharedMemorySize, GEMM_SMEM);
    cudaFuncSetAttribute(attn_kernel, cudaFuncAttributeMaxDynamicSharedMemorySize, ATTN_SMEM);

    const int NBIG = BB*LL*DMODEL/4;
    const int NW   = WSZ/4;
    CvtArgs ca;
    ca.src[0] = q;  ca.dst[0] = xq;         ca.n4[0] = NBIG;
    ca.src[1] = k;  ca.dst[1] = xk;         ca.n4[1] = NBIG;
    ca.src[2] = v;  ca.dst[2] = xv;         ca.n4[2] = NBIG;
    ca.src[3] = wq; ca.dst[3] = wh;         ca.n4[3] = NW;
    ca.src[4] = wk; ca.dst[4] = wh + WSZ;   ca.n4[4] = NW;
    ca.src[5] = wv; ca.dst[5] = wh + 2*WSZ; ca.n4[5] = NW;
    ca.src[6] = wo; ca.dst[6] = wh + 3*WSZ; ca.n4[6] = NW;
    cvt_kernel<<<dim3(256, 7), 256>>>(ca);

    coef_kernel<<<2, 1024>>>(tm, am);

    QkvArgs qkv;
    qkv.X[0] = xq; qkv.X[1] = xk; qkv.X[2] = xv;
    qkv.W[0] = wh; qkv.W[1] = wh + WSZ; qkv.W[2] = wh + 2*WSZ;
    qkv.bias[0] = bq; qkv.bias[1] = bk; qkv.bias[2] = bv;
    qkv.Y[0] = gq; qkv.Y[1] = gk; qkv.Y[2] = gv;
    qkv.mode[0] = 1; qkv.mode[1] = 2; qkv.mode[2] = 3;
    qkv.coef = gcoef;
    gemm_qkv<<<dim3(8, 32, 3), 256, GEMM_SMEM>>>(qkv);

    attn_kernel<<<dim3(16, 16), 256, ATTN_SMEM>>>();

    gemm_out<<<dim3(8, 32), 256, GEMM_SMEM>>>(gattn, wh + 3*WSZ, bo, out);
}